// round 3
// baseline (speedup 1.0000x reference)
#include <cuda_runtime.h>
#include <math.h>

// Problem constants (fixed by the dataset)
#define NTOK 32768
#define DDIM 512
#define KCB  1024
#define NQ   4

#define ROWS 64                  // rows per block in sinkhorn passes
#define NBLK (NTOK / ROWS)       // 512 blocks

// -------- scratch (static __device__ globals; no allocation allowed) --------
__device__ float g_A[(size_t)NTOK * KCB];      // exp(2G - ||E||^2), 134 MB
__device__ float g_resid[(size_t)NTOK * DDIM]; // running residual, 64 MB
__device__ float g_Enorm[KCB];
__device__ float g_colsum[KCB];
__device__ float g_colpart[(size_t)NBLK * KCB]; // deterministic colsum partials

// ---------------------------------------------------------------------------
// init: residual = x, out = 0
__global__ void init_kernel(const float* __restrict__ x, float* __restrict__ out) {
    int i = blockIdx.x * blockDim.x + threadIdx.x;
    if (i < NTOK * DDIM) {
        g_resid[i] = x[i];
        out[i] = 0.0f;
    }
}

// ---------------------------------------------------------------------------
// ||E_k||^2 per codebook row
__global__ void enorm_kernel(const float* __restrict__ E) {
    int k = blockIdx.x;
    int t = threadIdx.x; // 128 threads
    float s = 0.0f;
    const float* row = E + (size_t)k * DDIM;
    for (int d = t; d < DDIM; d += 128) {
        float v = row[d];
        s += v * v;
    }
    __shared__ float sh[128];
    sh[t] = s;
    __syncthreads();
    for (int o = 64; o > 0; o >>= 1) {
        if (t < o) sh[t] += sh[t + o];
        __syncthreads();
    }
    if (t == 0) g_Enorm[k] = sh[0];
}

// ---------------------------------------------------------------------------
// SGEMM: G = resid @ E^T  (both row-major, inner dim DDIM), epilogue
// A[n,k] = expf(2*G - Enorm[k]).  128x128x8 tile, 8x8 microtile, double-buffered.
#define BM 128
#define BN 128
#define BK 8

__global__ __launch_bounds__(256) void gemm_expA(const float* __restrict__ E) {
    __shared__ float As[2][BK][BM];
    __shared__ float Bs[2][BK][BN];

    const int tid  = threadIdx.x;
    const int row0 = blockIdx.y * BM;
    const int col0 = blockIdx.x * BN;

    const int lr = tid >> 1;          // 0..127 : tile row to load
    const int lc = (tid & 1) * 4;     // 0 or 4 : k-offset within BK

    const float* Rp = g_resid + (size_t)(row0 + lr) * DDIM + lc;
    const float* Ep = E       + (size_t)(col0 + lr) * DDIM + lc;

    const int tx = tid & 15;          // 16 col-threads
    const int ty = tid >> 4;          // 16 row-threads

    float acc[8][8];
#pragma unroll
    for (int m = 0; m < 8; m++)
#pragma unroll
        for (int n = 0; n < 8; n++) acc[m][n] = 0.0f;

    // preload step 0
    float4 ra = *(const float4*)(Rp);
    float4 rb = *(const float4*)(Ep);
    As[0][lc + 0][lr] = ra.x; As[0][lc + 1][lr] = ra.y;
    As[0][lc + 2][lr] = ra.z; As[0][lc + 3][lr] = ra.w;
    Bs[0][lc + 0][lr] = rb.x; Bs[0][lc + 1][lr] = rb.y;
    Bs[0][lc + 2][lr] = rb.z; Bs[0][lc + 3][lr] = rb.w;
    __syncthreads();

    const int nsteps = DDIM / BK; // 64
    for (int s = 0; s < nsteps; s++) {
        int cur = s & 1;
        int nxt = cur ^ 1;
        if (s + 1 < nsteps) {
            ra = *(const float4*)(Rp + (s + 1) * BK);
            rb = *(const float4*)(Ep + (s + 1) * BK);
        }
#pragma unroll
        for (int kk = 0; kk < BK; kk++) {
            float fragA[8], fragB[8];
#pragma unroll
            for (int m = 0; m < 8; m++) fragA[m] = As[cur][kk][ty * 8 + m];
#pragma unroll
            for (int n = 0; n < 8; n++) fragB[n] = Bs[cur][kk][tx * 8 + n];
#pragma unroll
            for (int m = 0; m < 8; m++)
#pragma unroll
                for (int n = 0; n < 8; n++) acc[m][n] += fragA[m] * fragB[n];
        }
        if (s + 1 < nsteps) {
            As[nxt][lc + 0][lr] = ra.x; As[nxt][lc + 1][lr] = ra.y;
            As[nxt][lc + 2][lr] = ra.z; As[nxt][lc + 3][lr] = ra.w;
            Bs[nxt][lc + 0][lr] = rb.x; Bs[nxt][lc + 1][lr] = rb.y;
            Bs[nxt][lc + 2][lr] = rb.z; Bs[nxt][lc + 3][lr] = rb.w;
        }
        __syncthreads();
    }

    // epilogue: A = exp(2G - ||E||^2)
#pragma unroll
    for (int m = 0; m < 8; m++) {
        int row = row0 + ty * 8 + m;
        float* outp = g_A + (size_t)row * KCB + col0 + tx * 8;
#pragma unroll
        for (int n = 0; n < 8; n++) {
            float en = g_Enorm[col0 + tx * 8 + n];
            outp[n] = expf(2.0f * acc[m][n] - en);
        }
    }
}

// ---------------------------------------------------------------------------
// One sinkhorn iteration, fused row+col pass over A.
//   c_k  = useC ? 1/(K * colsum_prev[k]) : 1
//   r_n  = 1/(B * sum_k A[n,k] c_k)          (rows fully inside the block)
//   colpart[b][k] = sum_{n in block} A[n,k] r_n   (deterministic partials)
__global__ __launch_bounds__(256) void rowcol_pass(int useC) {
    __shared__ __align__(16) float c_s[KCB];
    __shared__ float r_s[ROWS];
    const int tid = threadIdx.x;
    const int r0  = blockIdx.x * ROWS;

    if (useC) {
        for (int k = tid; k < KCB; k += 256)
            c_s[k] = 1.0f / (1024.0f * g_colsum[k]);
    } else {
        for (int k = tid; k < KCB; k += 256) c_s[k] = 1.0f;
    }
    __syncthreads();

    const int w = tid >> 5, lane = tid & 31;
    const float4* c4 = (const float4*)c_s;
#pragma unroll
    for (int i = 0; i < ROWS / 8; i++) { // 8 rows per warp
        int lrow = w * 8 + i;
        const float4* a4 = (const float4*)(g_A + (size_t)(r0 + lrow) * KCB);
        float s = 0.0f;
#pragma unroll
        for (int t = 0; t < 8; t++) {
            float4 a = a4[lane + t * 32];
            float4 c = c4[lane + t * 32];
            s += a.x * c.x + a.y * c.y + a.z * c.z + a.w * c.w;
        }
        for (int o = 16; o > 0; o >>= 1) s += __shfl_down_sync(0xffffffffu, s, o);
        if (lane == 0) r_s[lrow] = 1.0f / (32768.0f * s);
    }
    __syncthreads();

    // column partials (tile is L2-resident after row phase)
    for (int k = tid; k < KCB; k += 256) {
        float acc = 0.0f;
#pragma unroll 8
        for (int j = 0; j < ROWS; j++)
            acc += g_A[(size_t)(r0 + j) * KCB + k] * r_s[j];
        g_colpart[(size_t)blockIdx.x * KCB + k] = acc;
    }
}

// deterministic fixed-order reduction of column partials
__global__ void reduce_colsum() {
    int k = blockIdx.x;
    int t = threadIdx.x; // 128 threads
    float s = 0.0f;
    for (int b = t; b < NBLK; b += 128)
        s += g_colpart[(size_t)b * KCB + k];
    __shared__ float sh[128];
    sh[t] = s;
    __syncthreads();
    for (int o = 64; o > 0; o >>= 1) {
        if (t < o) sh[t] += sh[t + o];
        __syncthreads();
    }
    if (t == 0) g_colsum[k] = sh[0];
}

// ---------------------------------------------------------------------------
// Final pass: argmax_k A[n,k]*c3_k (first-index tie-break, matching jnp.argmax),
// then gather codebook row: out += E[idx], resid -= E[idx].
__global__ __launch_bounds__(256) void argmax_gather(const float* __restrict__ E,
                                                     float* __restrict__ out) {
    __shared__ __align__(16) float c_s[KCB];
    const int tid = threadIdx.x;
    const int r0  = blockIdx.x * ROWS;

    for (int k = tid; k < KCB; k += 256)
        c_s[k] = 1.0f / (1024.0f * g_colsum[k]);
    __syncthreads();

    const int w = tid >> 5, lane = tid & 31;
#pragma unroll
    for (int i = 0; i < ROWS / 8; i++) {
        int n = r0 + w * 8 + i;
        const float* a = g_A + (size_t)n * KCB;
        float best = -1e30f;
        int   bi   = 0;
#pragma unroll
        for (int t = 0; t < 8; t++) {
            int kbase = (lane + t * 32) * 4;   // ascending k within a lane
            float4 av = *(const float4*)(a + kbase);
            float4 cv = *(const float4*)(c_s + kbase);
            float v;
            v = av.x * cv.x; if (v > best) { best = v; bi = kbase + 0; }
            v = av.y * cv.y; if (v > best) { best = v; bi = kbase + 1; }
            v = av.z * cv.z; if (v > best) { best = v; bi = kbase + 2; }
            v = av.w * cv.w; if (v > best) { best = v; bi = kbase + 3; }
        }
        // warp argmax with first-index tie-break
        for (int o = 16; o > 0; o >>= 1) {
            float ov = __shfl_down_sync(0xffffffffu, best, o);
            int   oi = __shfl_down_sync(0xffffffffu, bi, o);
            if (ov > best || (ov == best && oi < bi)) { best = ov; bi = oi; }
        }
        bi = __shfl_sync(0xffffffffu, bi, 0);

        const float* e  = E + (size_t)bi * DDIM;
        float* rp = g_resid + (size_t)n * DDIM;
        float* op = out     + (size_t)n * DDIM;
        for (int d = lane; d < DDIM; d += 32) {
            float ev = e[d];
            rp[d] -= ev;
            op[d] += ev;
        }
    }
}

// ---------------------------------------------------------------------------
extern "C" void kernel_launch(void* const* d_in, const int* in_sizes, int n_in,
                              void* d_out, int out_size) {
    const float* x         = (const float*)d_in[0];
    const float* codebooks = (const float*)d_in[1];
    // d_in[2] = sigma: dead in forward (straight-through cancels y_soft exactly)
    float* out = (float*)d_out;

    init_kernel<<<(NTOK * DDIM + 255) / 256, 256>>>(x, out);

    for (int lvl = 0; lvl < NQ; lvl++) {
        const float* E = codebooks + (size_t)lvl * KCB * DDIM;

        enorm_kernel<<<KCB, 128>>>(E);

        dim3 grid(KCB / BN, NTOK / BM);
        gemm_expA<<<grid, 256>>>(E);

        // sinkhorn: 3 iterations of (row, col) as diagonal-scaling recursion
        rowcol_pass<<<NBLK, 256>>>(0);  // iter 1 (c = 1)
        reduce_colsum<<<KCB, 128>>>();
        rowcol_pass<<<NBLK, 256>>>(1);  // iter 2
        reduce_colsum<<<KCB, 128>>>();
        rowcol_pass<<<NBLK, 256>>>(1);  // iter 3
        reduce_colsum<<<KCB, 128>>>();

        argmax_gather<<<NBLK, 256>>>(E, out);
    }
}

// round 9
// speedup vs baseline: 1.3410x; 1.3410x over previous
#include <cuda_runtime.h>
#include <cuda_bf16.h>
#include <math.h>
#include <stdint.h>

// Problem constants (fixed by the dataset)
#define NTOK 32768
#define DDIM 512
#define KCB  1024
#define NQ   4

#define ROWS 64                  // rows per block in sinkhorn passes
#define NBLK (NTOK / ROWS)       // 512 blocks

// -------- scratch (static __device__ globals; no allocation allowed) --------
__device__ float g_A[(size_t)NTOK * KCB];      // exp(2G - ||E||^2), 134 MB
__device__ float g_resid[(size_t)NTOK * DDIM]; // running residual, 64 MB
__device__ float g_Enorm[KCB];
__device__ float g_colsum[KCB];
__device__ float g_colpart[(size_t)NBLK * KCB];
// bf16 3-way splits (hi/mid/lo, all normal-range) for 6-product fp32 emulation
__device__ __align__(256) __nv_bfloat16 g_Rs[3][(size_t)NTOK * DDIM];
__device__ __align__(256) __nv_bfloat16 g_Es[3][(size_t)NQ * KCB * DDIM];

// ---------------------------------------------------------------------------
__device__ __forceinline__ uint32_t smem_u32(const void* p) {
    uint32_t a;
    asm("{ .reg .u64 t; cvta.to.shared.u64 t, %1; cvt.u32.u64 %0, t; }"
        : "=r"(a) : "l"(p));
    return a;
}
__device__ __forceinline__ void cp16(uint32_t dst, const void* src) {
    asm volatile("cp.async.cg.shared.global [%0], [%1], 16;"
                 :: "r"(dst), "l"(src));
}
#define CP_COMMIT() asm volatile("cp.async.commit_group;")
#define CP_WAIT(n)  asm volatile("cp.async.wait_group %0;" :: "n"(n))

__device__ __forceinline__ void ldmx4(uint32_t* r, uint32_t addr) {
    asm volatile("ldmatrix.sync.aligned.m8n8.x4.shared.b16 {%0,%1,%2,%3}, [%4];"
                 : "=r"(r[0]), "=r"(r[1]), "=r"(r[2]), "=r"(r[3]) : "r"(addr));
}
__device__ __forceinline__ void mma16816bf(float* c, const uint32_t* a,
                                           const uint32_t* b) {
    asm volatile(
        "mma.sync.aligned.m16n8k16.row.col.f32.bf16.bf16.f32 "
        "{%0,%1,%2,%3}, {%4,%5,%6,%7}, {%8,%9}, {%0,%1,%2,%3};"
        : "+f"(c[0]), "+f"(c[1]), "+f"(c[2]), "+f"(c[3])
        : "r"(a[0]), "r"(a[1]), "r"(a[2]), "r"(a[3]), "r"(b[0]), "r"(b[1]));
}

// ---------------------------------------------------------------------------
// init: residual = x, out = 0
__global__ void init_kernel(const float* __restrict__ x, float* __restrict__ out) {
    int i = blockIdx.x * blockDim.x + threadIdx.x;
    if (i < NTOK * DDIM) {
        g_resid[i] = x[i];
        out[i] = 0.0f;
    }
}

// 3-way bf16 split (each remainder exact in fp32 by Sterbenz; bf16 range = fp32)
__global__ void split_R_kernel() {
    int i = blockIdx.x * blockDim.x + threadIdx.x;
    if (i < NTOK * DDIM) {
        float a = g_resid[i];
        __nv_bfloat16 h = __float2bfloat16(a);
        float r1 = a - __bfloat162float(h);
        __nv_bfloat16 m = __float2bfloat16(r1);
        float r2 = r1 - __bfloat162float(m);
        g_Rs[0][i] = h;
        g_Rs[1][i] = m;
        g_Rs[2][i] = __float2bfloat16(r2);
    }
}

__global__ void split_E_kernel(const float* __restrict__ codebooks) {
    int i = blockIdx.x * blockDim.x + threadIdx.x;
    if (i < NQ * KCB * DDIM) {
        float a = codebooks[i];
        __nv_bfloat16 h = __float2bfloat16(a);
        float r1 = a - __bfloat162float(h);
        __nv_bfloat16 m = __float2bfloat16(r1);
        float r2 = r1 - __bfloat162float(m);
        g_Es[0][i] = h;
        g_Es[1][i] = m;
        g_Es[2][i] = __float2bfloat16(r2);
    }
}

// ---------------------------------------------------------------------------
// ||E_k||^2 per codebook row (fp32, deterministic order)
__global__ void enorm_kernel(const float* __restrict__ E) {
    int k = blockIdx.x;
    int t = threadIdx.x; // 128
    float s = 0.0f;
    const float* row = E + (size_t)k * DDIM;
    for (int d = t; d < DDIM; d += 128) { float v = row[d]; s += v * v; }
    __shared__ float sh[128];
    sh[t] = s;
    __syncthreads();
    for (int o = 64; o > 0; o >>= 1) {
        if (t < o) sh[t] += sh[t + o];
        __syncthreads();
    }
    if (t == 0) g_Enorm[k] = sh[0];
}

// ---------------------------------------------------------------------------
// HMMA GEMM: G = sum of 6 bf16 plane-products (hh,hm,mh,mm,hl,lh),
// one bf16 GEMM with K = 6*512 = 3072 via plane concatenation.
// Block 128x128, BK=64, 8 warps (64x32 warp tiles), cp.async double buffer.
// Epilogue fused: g_A = exp(2G - ||E||^2).
#define BKH 64
#define KCHUNKS 48                      // 3072 / 64
#define ATILE_B 16384                   // 128 rows * 128 B
#define BUF_B   (2 * ATILE_B)           // A + B per stage
#define SMEM_GEMM (2 * BUF_B)           // 64 KB

__global__ __launch_bounds__(256) void gemm_hmma(int lvl) {
    extern __shared__ char sm[];
    const uint32_t sbase = smem_u32(sm);
    const int tid  = threadIdx.x;
    const int wid  = tid >> 5;
    const int lane = tid & 31;
    const int row0 = blockIdx.y * 128;  // token tile
    const int col0 = blockIdx.x * 128;  // codebook tile
    const size_t eoff = (size_t)lvl * KCB * DDIM;

    const int wm0 = (wid & 1) * 64;
    const int wn0 = (wid >> 1) * 32;

    float acc[4][4][4];
#pragma unroll
    for (int mt = 0; mt < 4; mt++)
#pragma unroll
        for (int nt = 0; nt < 4; nt++)
#pragma unroll
            for (int e = 0; e < 4; e++) acc[mt][nt][e] = 0.0f;

    // chunk kc: product p = kc>>3; A-plane PA[p], B-plane PB[p]
    //   p:  0  1  2  3  4  5
    //  PA:  h  h  m  m  h  l
    //  PB:  h  m  h  m  l  h
    auto issue_load = [&](int kc, int buf) {
        const int p  = kc >> 3;
        const int pa = (p == 2 || p == 3) ? 1 : (p == 5 ? 2 : 0);
        const int pb = (p == 1 || p == 3) ? 1 : (p == 4 ? 2 : 0);
        const __nv_bfloat16* Ap = g_Rs[pa];
        const __nv_bfloat16* Bp = g_Es[pb] + eoff;
        const int koff = (kc & 7) * BKH;
        uint32_t abase = sbase + buf * BUF_B;
        uint32_t bbase = abase + ATILE_B;
#pragma unroll
        for (int i = 0; i < 4; i++) {
            int u   = tid + i * 256;
            int rr  = u >> 3;
            int c16 = u & 7;
            uint32_t soff = rr * 128 + ((c16 ^ (rr & 7)) << 4);
            cp16(abase + soff, Ap + (size_t)(row0 + rr) * DDIM + koff + c16 * 8);
            cp16(bbase + soff, Bp + (size_t)(col0 + rr) * DDIM + koff + c16 * 8);
        }
        CP_COMMIT();
    };

    auto compute = [&](int buf) {
        uint32_t abase = sbase + buf * BUF_B;
        uint32_t bbase = abase + ATILE_B;
#pragma unroll
        for (int ks = 0; ks < 4; ks++) {
            uint32_t aF[4][4], bF[4][2];
            const int ga = ks * 2 + (lane >> 4);
#pragma unroll
            for (int mt = 0; mt < 4; mt++) {
                int row = wm0 + mt * 16 + (lane & 15);
                ldmx4(aF[mt], abase + row * 128 + ((ga ^ (row & 7)) << 4));
            }
#pragma unroll
            for (int bt = 0; bt < 2; bt++) {
                int nrow = wn0 + bt * 16 + (lane & 7) + ((lane >> 4) << 3);
                int gb   = ks * 2 + ((lane >> 3) & 1);
                uint32_t r[4];
                ldmx4(r, bbase + nrow * 128 + ((gb ^ (nrow & 7)) << 4));
                bF[bt * 2 + 0][0] = r[0]; bF[bt * 2 + 0][1] = r[1];
                bF[bt * 2 + 1][0] = r[2]; bF[bt * 2 + 1][1] = r[3];
            }
#pragma unroll
            for (int mt = 0; mt < 4; mt++)
#pragma unroll
                for (int nt = 0; nt < 4; nt++)
                    mma16816bf(acc[mt][nt], aF[mt], bF[nt]);
        }
    };

    issue_load(0, 0);
    for (int kc = 0; kc < KCHUNKS; kc++) {
        int buf = kc & 1;
        if (kc + 1 < KCHUNKS) {
            issue_load(kc + 1, buf ^ 1);
            CP_WAIT(1);
        } else {
            CP_WAIT(0);
        }
        __syncthreads();
        compute(buf);
        __syncthreads();
    }

    // epilogue: exp(2G - ||E||^2) -> g_A
#pragma unroll
    for (int nt = 0; nt < 4; nt++) {
        int col = col0 + wn0 + nt * 8 + (lane & 3) * 2;
        float en0 = __ldg(&g_Enorm[col]);
        float en1 = __ldg(&g_Enorm[col + 1]);
#pragma unroll
        for (int mt = 0; mt < 4; mt++) {
            int r0 = row0 + wm0 + mt * 16 + (lane >> 2);
            float2 v0, v1;
            v0.x = expf(2.0f * acc[mt][nt][0] - en0);
            v0.y = expf(2.0f * acc[mt][nt][1] - en1);
            v1.x = expf(2.0f * acc[mt][nt][2] - en0);
            v1.y = expf(2.0f * acc[mt][nt][3] - en1);
            *(float2*)(g_A + (size_t)r0 * KCB + col)       = v0;
            *(float2*)(g_A + (size_t)(r0 + 8) * KCB + col) = v1;
        }
    }
}

// ---------------------------------------------------------------------------
// One sinkhorn iteration, SINGLE pass over A (tiles kept in registers):
//   c_k = useC ? 1/(K * colsum_prev[k]) : 1
//   r_n = 1/(B * sum_k A[n,k] c_k)
//   colpart[b][k] = sum_{n in block} A[n,k] * r_n   (deterministic partials)
__global__ __launch_bounds__(256) void rowcol_pass(int useC) {
    __shared__ __align__(16) float c_s[KCB];
    __shared__ float wacc[8][KCB];   // per-warp column partials
    const int tid = threadIdx.x, w = tid >> 5, lane = tid & 31;
    const int r0 = blockIdx.x * ROWS;

    for (int k = tid; k < KCB; k += 256)
        c_s[k] = useC ? 1.0f / (1024.0f * g_colsum[k]) : 1.0f;
    __syncthreads();

    const float4* c4 = (const float4*)c_s;
    float4 acc[8];
#pragma unroll
    for (int t = 0; t < 8; t++) acc[t] = make_float4(0.f, 0.f, 0.f, 0.f);

#pragma unroll
    for (int i = 0; i < 8; i++) {        // 8 rows per warp
        int n = r0 + w * 8 + i;
        const float4* a4 = (const float4*)(g_A + (size_t)n * KCB);
        float4 a[8];
        float s = 0.0f;
#pragma unroll
        for (int t = 0; t < 8; t++) {
            a[t] = a4[lane + t * 32];
            float4 c = c4[lane + t * 32];
            s += a[t].x * c.x + a[t].y * c.y + a[t].z * c.z + a[t].w * c.w;
        }
        for (int o = 16; o > 0; o >>= 1) s += __shfl_down_sync(0xffffffffu, s, o);
        s = __shfl_sync(0xffffffffu, s, 0);
        float r = 1.0f / (32768.0f * s);
#pragma unroll
        for (int t = 0; t < 8; t++) {
            acc[t].x += a[t].x * r; acc[t].y += a[t].y * r;
            acc[t].z += a[t].z * r; acc[t].w += a[t].w * r;
        }
    }
    float4* wa4 = (float4*)wacc[w];
#pragma unroll
    for (int t = 0; t < 8; t++) wa4[lane + t * 32] = acc[t];
    __syncthreads();

    for (int k = tid; k < KCB; k += 256) {
        float sum = 0.0f;
#pragma unroll
        for (int ww = 0; ww < 8; ww++) sum += wacc[ww][k];
        g_colpart[(size_t)blockIdx.x * KCB + k] = sum;
    }
}

// deterministic fixed-order reduction of column partials
__global__ void reduce_colsum() {
    int k = blockIdx.x;
    int t = threadIdx.x; // 128
    float s = 0.0f;
    for (int b = t; b < NBLK; b += 128)
        s += g_colpart[(size_t)b * KCB + k];
    __shared__ float sh[128];
    sh[t] = s;
    __syncthreads();
    for (int o = 64; o > 0; o >>= 1) {
        if (t < o) sh[t] += sh[t + o];
        __syncthreads();
    }
    if (t == 0) g_colsum[k] = sh[0];
}

// ---------------------------------------------------------------------------
// Final pass: argmax_k A[n,k]*c3_k (first-index tie-break), then gather.
__global__ __launch_bounds__(256) void argmax_gather(const float* __restrict__ E,
                                                     float* __restrict__ out) {
    __shared__ __align__(16) float c_s[KCB];
    const int tid = threadIdx.x;
    const int r0  = blockIdx.x * ROWS;

    for (int k = tid; k < KCB; k += 256)
        c_s[k] = 1.0f / (1024.0f * g_colsum[k]);
    __syncthreads();

    const int w = tid >> 5, lane = tid & 31;
#pragma unroll
    for (int i = 0; i < ROWS / 8; i++) {
        int n = r0 + w * 8 + i;
        const float* a = g_A + (size_t)n * KCB;
        float best = -1e30f;
        int   bi   = 0;
#pragma unroll
        for (int t = 0; t < 8; t++) {
            int kbase = (lane + t * 32) * 4;
            float4 av = *(const float4*)(a + kbase);
            float4 cv = *(const float4*)(c_s + kbase);
            float v;
            v = av.x * cv.x; if (v > best) { best = v; bi = kbase + 0; }
            v = av.y * cv.y; if (v > best) { best = v; bi = kbase + 1; }
            v = av.z * cv.z; if (v > best) { best = v; bi = kbase + 2; }
            v = av.w * cv.w; if (v > best) { best = v; bi = kbase + 3; }
        }
        for (int o = 16; o > 0; o >>= 1) {
            float ov = __shfl_down_sync(0xffffffffu, best, o);
            int   oi = __shfl_down_sync(0xffffffffu, bi, o);
            if (ov > best || (ov == best && oi < bi)) { best = ov; bi = oi; }
        }
        bi = __shfl_sync(0xffffffffu, bi, 0);

        const float* e  = E + (size_t)bi * DDIM;
        float* rp = g_resid + (size_t)n * DDIM;
        float* op = out     + (size_t)n * DDIM;
        for (int d = lane; d < DDIM; d += 32) {
            float ev = e[d];
            rp[d] -= ev;
            op[d] += ev;
        }
    }
}

// ---------------------------------------------------------------------------
extern "C" void kernel_launch(void* const* d_in, const int* in_sizes, int n_in,
                              void* d_out, int out_size) {
    const float* x         = (const float*)d_in[0];
    const float* codebooks = (const float*)d_in[1];
    // d_in[2] = sigma: dead in forward (straight-through cancels y_soft exactly)
    float* out = (float*)d_out;

    static int smem_set = 0;
    if (!smem_set) {
        cudaFuncSetAttribute(gemm_hmma,
                             cudaFuncAttributeMaxDynamicSharedMemorySize,
                             SMEM_GEMM);
        smem_set = 1;
    }

    init_kernel<<<(NTOK * DDIM + 255) / 256, 256>>>(x, out);
    split_E_kernel<<<(NQ * KCB * DDIM + 255) / 256, 256>>>(codebooks);

    for (int lvl = 0; lvl < NQ; lvl++) {
        const float* E = codebooks + (size_t)lvl * KCB * DDIM;

        split_R_kernel<<<(NTOK * DDIM + 255) / 256, 256>>>();
        enorm_kernel<<<KCB, 128>>>(E);

        gemm_hmma<<<dim3(KCB / 128, NTOK / 128), 256, SMEM_GEMM>>>(lvl);

        rowcol_pass<<<NBLK, 256>>>(0);
        reduce_colsum<<<KCB, 128>>>();
        rowcol_pass<<<NBLK, 256>>>(1);
        reduce_colsum<<<KCB, 128>>>();
        rowcol_pass<<<NBLK, 256>>>(1);
        reduce_colsum<<<KCB, 128>>>();

        argmax_gather<<<NBLK, 256>>>(E, out);
    }
}

// round 11
// speedup vs baseline: 1.7162x; 1.2798x over previous
#include <cuda_runtime.h>
#include <cuda_bf16.h>
#include <math.h>
#include <stdint.h>

// Problem constants (fixed by the dataset)
#define NTOK 32768
#define DDIM 512
#define KCB  1024
#define NQ   4

#define ROWS 64                  // rows per block in sinkhorn passes
#define NBLK (NTOK / ROWS)       // 512 blocks

// -------- scratch (static __device__ globals; no allocation allowed) --------
__device__ float g_A[(size_t)NTOK * KCB];      // exp(2G - ||E||^2), 134 MB
__device__ float g_resid[(size_t)NTOK * DDIM]; // running residual, 64 MB
__device__ float g_Enorm[KCB];
__device__ float g_colsum[KCB];
__device__ float g_colpart[(size_t)NBLK * KCB];
// bf16 3-way splits (hi/mid/lo, all normal-range) for 6-product fp32 emulation
__device__ __align__(256) __nv_bfloat16 g_Rs[3][(size_t)NTOK * DDIM];
__device__ __align__(256) __nv_bfloat16 g_Es[3][(size_t)NQ * KCB * DDIM];

// ---------------------------------------------------------------------------
__device__ __forceinline__ uint32_t smem_u32(const void* p) {
    uint32_t a;
    asm("{ .reg .u64 t; cvta.to.shared.u64 t, %1; cvt.u32.u64 %0, t; }"
        : "=r"(a) : "l"(p));
    return a;
}
__device__ __forceinline__ void cp16(uint32_t dst, const void* src) {
    asm volatile("cp.async.cg.shared.global [%0], [%1], 16;"
                 :: "r"(dst), "l"(src));
}
#define CP_COMMIT() asm volatile("cp.async.commit_group;")
#define CP_WAIT(n)  asm volatile("cp.async.wait_group %0;" :: "n"(n))

__device__ __forceinline__ void ldmx4(uint32_t* r, uint32_t addr) {
    asm volatile("ldmatrix.sync.aligned.m8n8.x4.shared.b16 {%0,%1,%2,%3}, [%4];"
                 : "=r"(r[0]), "=r"(r[1]), "=r"(r[2]), "=r"(r[3]) : "r"(addr));
}
__device__ __forceinline__ void mma16816bf(float* c, const uint32_t* a,
                                           const uint32_t* b) {
    asm volatile(
        "mma.sync.aligned.m16n8k16.row.col.f32.bf16.bf16.f32 "
        "{%0,%1,%2,%3}, {%4,%5,%6,%7}, {%8,%9}, {%0,%1,%2,%3};"
        : "+f"(c[0]), "+f"(c[1]), "+f"(c[2]), "+f"(c[3])
        : "r"(a[0]), "r"(a[1]), "r"(a[2]), "r"(a[3]), "r"(b[0]), "r"(b[1]));
}

// 3-way bf16 split (remainders exact in fp32; bf16 range = fp32, no subnormals)
__device__ __forceinline__ void split3(float a, __nv_bfloat16& h,
                                       __nv_bfloat16& m, __nv_bfloat16& l) {
    h = __float2bfloat16(a);
    float r1 = a - __bfloat162float(h);
    m = __float2bfloat16(r1);
    float r2 = r1 - __bfloat162float(m);
    l = __float2bfloat16(r2);
}

// ---------------------------------------------------------------------------
// init: residual = x, out = 0, level-0 split of x (fused)
__global__ void init_kernel(const float* __restrict__ x, float* __restrict__ out) {
    int i = blockIdx.x * blockDim.x + threadIdx.x;
    if (i < NTOK * DDIM) {
        float a = x[i];
        g_resid[i] = a;
        out[i] = 0.0f;
        __nv_bfloat16 h, m, l;
        split3(a, h, m, l);
        g_Rs[0][i] = h;
        g_Rs[1][i] = m;
        g_Rs[2][i] = l;
    }
}

// split all codebooks once per launch
__global__ void split_E_kernel(const float* __restrict__ codebooks) {
    int i = blockIdx.x * blockDim.x + threadIdx.x;
    if (i < NQ * KCB * DDIM) {
        __nv_bfloat16 h, m, l;
        split3(codebooks[i], h, m, l);
        g_Es[0][i] = h;
        g_Es[1][i] = m;
        g_Es[2][i] = l;
    }
}

// ---------------------------------------------------------------------------
// ||E_k||^2 per codebook row (fp32, deterministic order)
__global__ void enorm_kernel(const float* __restrict__ E) {
    int k = blockIdx.x;
    int t = threadIdx.x; // 128
    float s = 0.0f;
    const float* row = E + (size_t)k * DDIM;
    for (int d = t; d < DDIM; d += 128) { float v = row[d]; s += v * v; }
    __shared__ float sh[128];
    sh[t] = s;
    __syncthreads();
    for (int o = 64; o > 0; o >>= 1) {
        if (t < o) sh[t] += sh[t + o];
        __syncthreads();
    }
    if (t == 0) g_Enorm[k] = sh[0];
}

// ---------------------------------------------------------------------------
// HMMA GEMM: G = sum of 6 bf16 plane-products (hh,hm,mh,mm,hl,lh),
// K_phys = 6*512 = 3072, BK=64 -> 48 chunks. 3-stage cp.async ring with a
// single __syncthreads per chunk. Epilogue fused: g_A = exp(2G - ||E||^2).
#define BKH 64
#define KCHUNKS 48
#define ATILE_B 16384                   // 128 rows * 128 B
#define BUF_B   (2 * ATILE_B)           // A + B per stage (32 KB)
#define NSTAGE  3
#define SMEM_GEMM (NSTAGE * BUF_B)      // 96 KB

__global__ __launch_bounds__(256, 2) void gemm_hmma(int lvl) {
    extern __shared__ char sm[];
    const uint32_t sbase = smem_u32(sm);
    const int tid  = threadIdx.x;
    const int wid  = tid >> 5;
    const int lane = tid & 31;
    const int row0 = blockIdx.y * 128;  // token tile
    const int col0 = blockIdx.x * 128;  // codebook tile
    const size_t eoff = (size_t)lvl * KCB * DDIM;

    const int wm0 = (wid & 1) * 64;
    const int wn0 = (wid >> 1) * 32;

    float acc[4][4][4];
#pragma unroll
    for (int mt = 0; mt < 4; mt++)
#pragma unroll
        for (int nt = 0; nt < 4; nt++)
#pragma unroll
            for (int e = 0; e < 4; e++) acc[mt][nt][e] = 0.0f;

    // chunk kc: product p = kc>>3; planes: PA = h h m m h l ; PB = h m h m l h
    auto issue_load = [&](int kc, int slot) {
        const int p  = kc >> 3;
        const int pa = (p == 2 || p == 3) ? 1 : (p == 5 ? 2 : 0);
        const int pb = (p == 1 || p == 3) ? 1 : (p == 4 ? 2 : 0);
        const __nv_bfloat16* Ap = g_Rs[pa];
        const __nv_bfloat16* Bp = g_Es[pb] + eoff;
        const int koff = (kc & 7) * BKH;
        uint32_t abase = sbase + slot * BUF_B;
        uint32_t bbase = abase + ATILE_B;
#pragma unroll
        for (int i = 0; i < 4; i++) {
            int u   = tid + i * 256;
            int rr  = u >> 3;
            int c16 = u & 7;
            uint32_t soff = rr * 128 + ((c16 ^ (rr & 7)) << 4);
            cp16(abase + soff, Ap + (size_t)(row0 + rr) * DDIM + koff + c16 * 8);
            cp16(bbase + soff, Bp + (size_t)(col0 + rr) * DDIM + koff + c16 * 8);
        }
        CP_COMMIT();
    };

    auto compute = [&](int slot) {
        uint32_t abase = sbase + slot * BUF_B;
        uint32_t bbase = abase + ATILE_B;
#pragma unroll
        for (int ks = 0; ks < 4; ks++) {
            uint32_t aF[4][4], bF[4][2];
            const int ga = ks * 2 + (lane >> 4);
#pragma unroll
            for (int mt = 0; mt < 4; mt++) {
                int row = wm0 + mt * 16 + (lane & 15);
                ldmx4(aF[mt], abase + row * 128 + ((ga ^ (row & 7)) << 4));
            }
#pragma unroll
            for (int bt = 0; bt < 2; bt++) {
                int nrow = wn0 + bt * 16 + (lane & 7) + ((lane >> 4) << 3);
                int gb   = ks * 2 + ((lane >> 3) & 1);
                uint32_t r[4];
                ldmx4(r, bbase + nrow * 128 + ((gb ^ (nrow & 7)) << 4));
                bF[bt * 2 + 0][0] = r[0]; bF[bt * 2 + 0][1] = r[1];
                bF[bt * 2 + 1][0] = r[2]; bF[bt * 2 + 1][1] = r[3];
            }
#pragma unroll
            for (int mt = 0; mt < 4; mt++)
#pragma unroll
                for (int nt = 0; nt < 4; nt++)
                    mma16816bf(acc[mt][nt], aF[mt], bF[nt]);
        }
    };

    issue_load(0, 0);
    issue_load(1, 1);
    for (int kc = 0; kc < KCHUNKS; kc++) {
        CP_WAIT(1);             // this thread's group kc has landed
        __syncthreads();        // all threads waited AND finished compute(kc-1)
        if (kc + 2 < KCHUNKS) issue_load(kc + 2, (kc + 2) % NSTAGE);
        compute(kc % NSTAGE);
    }

    // epilogue: exp(2G - ||E||^2) -> g_A
#pragma unroll
    for (int nt = 0; nt < 4; nt++) {
        int col = col0 + wn0 + nt * 8 + (lane & 3) * 2;
        float en0 = __ldg(&g_Enorm[col]);
        float en1 = __ldg(&g_Enorm[col + 1]);
#pragma unroll
        for (int mt = 0; mt < 4; mt++) {
            int r0 = row0 + wm0 + mt * 16 + (lane >> 2);
            float2 v0, v1;
            v0.x = expf(2.0f * acc[mt][nt][0] - en0);
            v0.y = expf(2.0f * acc[mt][nt][1] - en1);
            v1.x = expf(2.0f * acc[mt][nt][2] - en0);
            v1.y = expf(2.0f * acc[mt][nt][3] - en1);
            *(float2*)(g_A + (size_t)r0 * KCB + col)       = v0;
            *(float2*)(g_A + (size_t)(r0 + 8) * KCB + col) = v1;
        }
    }
}

// ---------------------------------------------------------------------------
// One sinkhorn iteration, SINGLE pass over A (tiles kept in registers):
//   c_k = useC ? 1/(K * colsum_prev[k]) : 1
//   r_n = 1/(B * sum_k A[n,k] c_k)
//   colpart[b][k] = sum_{n in block} A[n,k] * r_n   (deterministic partials)
__global__ __launch_bounds__(256) void rowcol_pass(int useC) {
    __shared__ __align__(16) float c_s[KCB];
    __shared__ float wacc[8][KCB];   // per-warp column partials
    const int tid = threadIdx.x, w = tid >> 5, lane = tid & 31;
    const int r0 = blockIdx.x * ROWS;

    for (int k = tid; k < KCB; k += 256)
        c_s[k] = useC ? 1.0f / (1024.0f * g_colsum[k]) : 1.0f;
    __syncthreads();

    const float4* c4 = (const float4*)c_s;
    float4 acc[8];
#pragma unroll
    for (int t = 0; t < 8; t++) acc[t] = make_float4(0.f, 0.f, 0.f, 0.f);

#pragma unroll
    for (int i = 0; i < 8; i++) {        // 8 rows per warp
        int n = r0 + w * 8 + i;
        const float4* a4 = (const float4*)(g_A + (size_t)n * KCB);
        float4 a[8];
        float s = 0.0f;
#pragma unroll
        for (int t = 0; t < 8; t++) {
            a[t] = a4[lane + t * 32];
            float4 c = c4[lane + t * 32];
            s += a[t].x * c.x + a[t].y * c.y + a[t].z * c.z + a[t].w * c.w;
        }
        for (int o = 16; o > 0; o >>= 1) s += __shfl_down_sync(0xffffffffu, s, o);
        s = __shfl_sync(0xffffffffu, s, 0);
        float r = 1.0f / (32768.0f * s);
#pragma unroll
        for (int t = 0; t < 8; t++) {
            acc[t].x += a[t].x * r; acc[t].y += a[t].y * r;
            acc[t].z += a[t].z * r; acc[t].w += a[t].w * r;
        }
    }
    float4* wa4 = (float4*)wacc[w];
#pragma unroll
    for (int t = 0; t < 8; t++) wa4[lane + t * 32] = acc[t];
    __syncthreads();

    for (int k = tid; k < KCB; k += 256) {
        float sum = 0.0f;
#pragma unroll
        for (int ww = 0; ww < 8; ww++) sum += wacc[ww][k];
        g_colpart[(size_t)blockIdx.x * KCB + k] = sum;
    }
}

// deterministic fixed-order reduction of column partials
__global__ void reduce_colsum() {
    int k = blockIdx.x;
    int t = threadIdx.x; // 128
    float s = 0.0f;
    for (int b = t; b < NBLK; b += 128)
        s += g_colpart[(size_t)b * KCB + k];
    __shared__ float sh[128];
    sh[t] = s;
    __syncthreads();
    for (int o = 64; o > 0; o >>= 1) {
        if (t < o) sh[t] += sh[t + o];
        __syncthreads();
    }
    if (t == 0) g_colsum[k] = sh[0];
}

// ---------------------------------------------------------------------------
// Final pass: argmax_k A[n,k]*c3_k (first-index tie-break), gather codeword,
// update out/residual, and write the NEXT level's bf16 3-plane split (fused).
__global__ __launch_bounds__(256) void argmax_gather(const float* __restrict__ E,
                                                     float* __restrict__ out) {
    __shared__ __align__(16) float c_s[KCB];
    const int tid = threadIdx.x;
    const int r0  = blockIdx.x * ROWS;

    for (int k = tid; k < KCB; k += 256)
        c_s[k] = 1.0f / (1024.0f * g_colsum[k]);
    __syncthreads();

    const int w = tid >> 5, lane = tid & 31;
#pragma unroll
    for (int i = 0; i < ROWS / 8; i++) {
        int n = r0 + w * 8 + i;
        const float* a = g_A + (size_t)n * KCB;
        float best = -1e30f;
        int   bi   = 0;
#pragma unroll
        for (int t = 0; t < 8; t++) {
            int kbase = (lane + t * 32) * 4;
            float4 av = *(const float4*)(a + kbase);
            float4 cv = *(const float4*)(c_s + kbase);
            float v;
            v = av.x * cv.x; if (v > best) { best = v; bi = kbase + 0; }
            v = av.y * cv.y; if (v > best) { best = v; bi = kbase + 1; }
            v = av.z * cv.z; if (v > best) { best = v; bi = kbase + 2; }
            v = av.w * cv.w; if (v > best) { best = v; bi = kbase + 3; }
        }
        for (int o = 16; o > 0; o >>= 1) {
            float ov = __shfl_down_sync(0xffffffffu, best, o);
            int   oi = __shfl_down_sync(0xffffffffu, bi, o);
            if (ov > best || (ov == best && oi < bi)) { best = ov; bi = oi; }
        }
        bi = __shfl_sync(0xffffffffu, bi, 0);

        // each lane owns 16 contiguous dims -> coalesced fp32 & bf16 traffic
        const int d0 = lane * 16;
        const float4* e4  = (const float4*)(E + (size_t)bi * DDIM + d0);
        float4* rp4 = (float4*)(g_resid + (size_t)n * DDIM + d0);
        float4* op4 = (float4*)(out     + (size_t)n * DDIM + d0);
        uint32_t hw[8], mw[8], lw[8];
#pragma unroll
        for (int j = 0; j < 4; j++) {
            float4 ev = e4[j];
            float4 rv = rp4[j];
            rv.x -= ev.x; rv.y -= ev.y; rv.z -= ev.z; rv.w -= ev.w;
            rp4[j] = rv;
            float4 ov = op4[j];
            ov.x += ev.x; ov.y += ev.y; ov.z += ev.z; ov.w += ev.w;
            op4[j] = ov;
            __nv_bfloat16 h0, m0, l0, h1, m1, l1, h2, m2, l2, h3, m3, l3;
            split3(rv.x, h0, m0, l0); split3(rv.y, h1, m1, l1);
            split3(rv.z, h2, m2, l2); split3(rv.w, h3, m3, l3);
            __nv_bfloat162 hp0 = __halves2bfloat162(h0, h1), hp1 = __halves2bfloat162(h2, h3);
            __nv_bfloat162 mp0 = __halves2bfloat162(m0, m1), mp1 = __halves2bfloat162(m2, m3);
            __nv_bfloat162 lp0 = __halves2bfloat162(l0, l1), lp1 = __halves2bfloat162(l2, l3);
            hw[j * 2 + 0] = *(uint32_t*)&hp0; hw[j * 2 + 1] = *(uint32_t*)&hp1;
            mw[j * 2 + 0] = *(uint32_t*)&mp0; mw[j * 2 + 1] = *(uint32_t*)&mp1;
            lw[j * 2 + 0] = *(uint32_t*)&lp0; lw[j * 2 + 1] = *(uint32_t*)&lp1;
        }
        uint4* hdst = (uint4*)(g_Rs[0] + (size_t)n * DDIM + d0);
        uint4* mdst = (uint4*)(g_Rs[1] + (size_t)n * DDIM + d0);
        uint4* ldst = (uint4*)(g_Rs[2] + (size_t)n * DDIM + d0);
        hdst[0] = make_uint4(hw[0], hw[1], hw[2], hw[3]);
        hdst[1] = make_uint4(hw[4], hw[5], hw[6], hw[7]);
        mdst[0] = make_uint4(mw[0], mw[1], mw[2], mw[3]);
        mdst[1] = make_uint4(mw[4], mw[5], mw[6], mw[7]);
        ldst[0] = make_uint4(lw[0], lw[1], lw[2], lw[3]);
        ldst[1] = make_uint4(lw[4], lw[5], lw[6], lw[7]);
    }
}

// ---------------------------------------------------------------------------
extern "C" void kernel_launch(void* const* d_in, const int* in_sizes, int n_in,
                              void* d_out, int out_size) {
    const float* x         = (const float*)d_in[0];
    const float* codebooks = (const float*)d_in[1];
    // d_in[2] = sigma: dead in forward (straight-through cancels y_soft exactly)
    float* out = (float*)d_out;

    static int smem_set = 0;
    if (!smem_set) {
        cudaFuncSetAttribute(gemm_hmma,
                             cudaFuncAttributeMaxDynamicSharedMemorySize,
                             SMEM_GEMM);
        smem_set = 1;
    }

    init_kernel<<<(NTOK * DDIM + 255) / 256, 256>>>(x, out);
    split_E_kernel<<<(NQ * KCB * DDIM + 255) / 256, 256>>>(codebooks);

    for (int lvl = 0; lvl < NQ; lvl++) {
        const float* E = codebooks + (size_t)lvl * KCB * DDIM;

        enorm_kernel<<<KCB, 128>>>(E);

        gemm_hmma<<<dim3(KCB / 128, NTOK / 128), 256, SMEM_GEMM>>>(lvl);

        rowcol_pass<<<NBLK, 256>>>(0);
        reduce_colsum<<<KCB, 128>>>();
        rowcol_pass<<<NBLK, 256>>>(1);
        reduce_colsum<<<KCB, 128>>>();
        rowcol_pass<<<NBLK, 256>>>(1);
        reduce_colsum<<<KCB, 128>>>();

        argmax_gather<<<NBLK, 256>>>(E, out);
    }
}

// round 13
// speedup vs baseline: 1.7876x; 1.0416x over previous
#include <cuda_runtime.h>
#include <cuda_bf16.h>
#include <math.h>
#include <stdint.h>

// Problem constants (fixed by the dataset)
#define NTOK 32768
#define DDIM 512
#define KCB  1024
#define NQ   4

#define ROWS 64                  // rows per block in sinkhorn passes
#define NBLK (NTOK / ROWS)       // 512 blocks

// -------- scratch (static __device__ globals; no allocation allowed) --------
__device__ float g_A[(size_t)NTOK * KCB];      // exp(2G - ||E||^2), 134 MB
__device__ float g_resid[(size_t)NTOK * DDIM]; // running residual, 64 MB
__device__ float g_Enorm[KCB];
__device__ float g_colsum[KCB];
__device__ float g_colpart[(size_t)NBLK * KCB];
// bf16 3-way splits (hi/mid/lo, all normal-range) for 6-product fp32 emulation
__device__ __align__(256) __nv_bfloat16 g_Rs[3][(size_t)NTOK * DDIM];
__device__ __align__(256) __nv_bfloat16 g_Es[3][(size_t)NQ * KCB * DDIM];

// ---------------------------------------------------------------------------
__device__ __forceinline__ uint32_t smem_u32(const void* p) {
    uint32_t a;
    asm("{ .reg .u64 t; cvta.to.shared.u64 t, %1; cvt.u32.u64 %0, t; }"
        : "=r"(a) : "l"(p));
    return a;
}
__device__ __forceinline__ void cp16(uint32_t dst, const void* src) {
    asm volatile("cp.async.cg.shared.global [%0], [%1], 16;"
                 :: "r"(dst), "l"(src));
}
#define CP_COMMIT() asm volatile("cp.async.commit_group;")
#define CP_WAIT(n)  asm volatile("cp.async.wait_group %0;" :: "n"(n))

__device__ __forceinline__ void ldmx4(uint32_t* r, uint32_t addr) {
    asm volatile("ldmatrix.sync.aligned.m8n8.x4.shared.b16 {%0,%1,%2,%3}, [%4];"
                 : "=r"(r[0]), "=r"(r[1]), "=r"(r[2]), "=r"(r[3]) : "r"(addr));
}
__device__ __forceinline__ void mma16816bf(float* c, const uint32_t* a,
                                           const uint32_t* b) {
    asm volatile(
        "mma.sync.aligned.m16n8k16.row.col.f32.bf16.bf16.f32 "
        "{%0,%1,%2,%3}, {%4,%5,%6,%7}, {%8,%9}, {%0,%1,%2,%3};"
        : "+f"(c[0]), "+f"(c[1]), "+f"(c[2]), "+f"(c[3])
        : "r"(a[0]), "r"(a[1]), "r"(a[2]), "r"(a[3]), "r"(b[0]), "r"(b[1]));
}

// 3-way bf16 split (remainders exact in fp32; bf16 range = fp32, no subnormals)
__device__ __forceinline__ void split3(float a, __nv_bfloat16& h,
                                       __nv_bfloat16& m, __nv_bfloat16& l) {
    h = __float2bfloat16(a);
    float r1 = a - __bfloat162float(h);
    m = __float2bfloat16(r1);
    float r2 = r1 - __bfloat162float(m);
    l = __float2bfloat16(r2);
}

// ---------------------------------------------------------------------------
// init: residual = x, out = 0, level-0 split of x (fused)
__global__ void init_kernel(const float* __restrict__ x, float* __restrict__ out) {
    int i = blockIdx.x * blockDim.x + threadIdx.x;
    if (i < NTOK * DDIM) {
        float a = x[i];
        g_resid[i] = a;
        out[i] = 0.0f;
        __nv_bfloat16 h, m, l;
        split3(a, h, m, l);
        g_Rs[0][i] = h;
        g_Rs[1][i] = m;
        g_Rs[2][i] = l;
    }
}

// split all codebooks once per launch
__global__ void split_E_kernel(const float* __restrict__ codebooks) {
    int i = blockIdx.x * blockDim.x + threadIdx.x;
    if (i < NQ * KCB * DDIM) {
        __nv_bfloat16 h, m, l;
        split3(codebooks[i], h, m, l);
        g_Es[0][i] = h;
        g_Es[1][i] = m;
        g_Es[2][i] = l;
    }
}

// ---------------------------------------------------------------------------
// ||E_k||^2 per codebook row (fp32, deterministic order)
__global__ void enorm_kernel(const float* __restrict__ E) {
    int k = blockIdx.x;
    int t = threadIdx.x; // 128
    float s = 0.0f;
    const float* row = E + (size_t)k * DDIM;
    for (int d = t; d < DDIM; d += 128) { float v = row[d]; s += v * v; }
    __shared__ float sh[128];
    sh[t] = s;
    __syncthreads();
    for (int o = 64; o > 0; o >>= 1) {
        if (t < o) sh[t] += sh[t + o];
        __syncthreads();
    }
    if (t == 0) g_Enorm[k] = sh[0];
}

// ---------------------------------------------------------------------------
// HMMA GEMM: G = sum of 6 bf16 plane-products (hh,hm,mh,mm,hl,lh).
// Stage = one physical k32 slice holding ALL 6 planes as 3 pair-tiles
// (128 rows x 128 B, SW swizzle): T0=(Rh|Rm) T1=(Rl|Eh) T2=(Em|El).
// Per k16 step: A fragments loaded once per plane, B fragments for all 3
// planes kept in registers -> LDSM halved, STS halved vs plane-major.
// 16 stages, 2-stage cp.async ring. Epilogue fused: g_A = exp(2G - ||E||^2).
#define TILE_B  16384                   // 128 rows * 128 B
#define BUF_B   (3 * TILE_B)            // 48 KB per stage
#define NSTAGE  2
#define NHC     16                      // 512 / 32 half-chunks
#define SMEM_GEMM (NSTAGE * BUF_B)      // 96 KB

__global__ __launch_bounds__(256, 2) void gemm_hmma(int lvl) {
    extern __shared__ char sm[];
    const uint32_t sbase = smem_u32(sm);
    const int tid  = threadIdx.x;
    const int wid  = tid >> 5;
    const int lane = tid & 31;
    const int row0 = blockIdx.y * 128;  // token tile
    const int col0 = blockIdx.x * 128;  // codebook tile
    const size_t eoff = (size_t)lvl * KCB * DDIM;

    const int wm0 = (wid & 1) * 64;
    const int wn0 = (wid >> 1) * 32;

    float acc[4][4][4];
#pragma unroll
    for (int mt = 0; mt < 4; mt++)
#pragma unroll
        for (int nt = 0; nt < 4; nt++)
#pragma unroll
            for (int e = 0; e < 4; e++) acc[mt][nt][e] = 0.0f;

    // plane table: 0..2 = Rh,Rm,Rl (token rows); 3..5 = Eh,Em,El (codebook rows)
    const __nv_bfloat16* plane[6] = {
        g_Rs[0], g_Rs[1], g_Rs[2],
        g_Es[0] + eoff, g_Es[1] + eoff, g_Es[2] + eoff
    };

    // stage hc: pair-tile t holds planes (2t | 2t+1); left half = 4x16B units
    auto issue_load = [&](int hc, int slot) {
        const int koff = hc * 32;
        const uint32_t dbase = sbase + slot * BUF_B;
#pragma unroll
        for (int i = 0; i < 12; i++) {
            int v   = tid + i * 256;
            int t   = v >> 10;           // tile 0..2
            int rr  = (v >> 3) & 127;    // row
            int c16 = v & 7;             // 16B unit
            int p   = t * 2 + (c16 >> 2);
            int rb  = (p >= 3) ? col0 : row0;
            const __nv_bfloat16* src =
                plane[p] + (size_t)(rb + rr) * DDIM + koff + (c16 & 3) * 8;
            uint32_t dst = dbase + t * TILE_B + rr * 128 + ((c16 ^ (rr & 7)) << 4);
            cp16(dst, src);
        }
        CP_COMMIT();
    };

    auto compute = [&](int slot) {
        const uint32_t t0 = sbase + slot * BUF_B;
        const uint32_t t1 = t0 + TILE_B;
        const uint32_t t2 = t1 + TILE_B;
#pragma unroll
        for (int ks = 0; ks < 2; ks++) {
            const int au = ks * 2 + (lane >> 4);        // A unit within half
            const int bu = ks * 2 + ((lane >> 3) & 1);  // B unit within half

            uint32_t aF[4][4], bH[4][2], bM[4][2], bL[4][2];

            // B fragment loader: tile + half (0 = units 0..3, 1 = units 4..7)
            auto loadB = [&](uint32_t (*dst)[2], uint32_t tile, int half) {
#pragma unroll
                for (int bt = 0; bt < 2; bt++) {
                    int nrow = wn0 + bt * 16 + (lane & 7) + ((lane >> 4) << 3);
                    int u = half * 4 + bu;
                    uint32_t r[4];
                    ldmx4(r, tile + nrow * 128 + ((u ^ (nrow & 7)) << 4));
                    dst[bt * 2 + 0][0] = r[0]; dst[bt * 2 + 0][1] = r[1];
                    dst[bt * 2 + 1][0] = r[2]; dst[bt * 2 + 1][1] = r[3];
                }
            };
            auto loadA = [&](uint32_t tile, int half) {
#pragma unroll
                for (int mt = 0; mt < 4; mt++) {
                    int row = wm0 + mt * 16 + (lane & 15);
                    int u = half * 4 + au;
                    ldmx4(aF[mt], tile + row * 128 + ((u ^ (row & 7)) << 4));
                }
            };
            auto mmaAll = [&](uint32_t (*bF)[2]) {
#pragma unroll
                for (int mt = 0; mt < 4; mt++)
#pragma unroll
                    for (int nt = 0; nt < 4; nt++)
                        mma16816bf(acc[mt][nt], aF[mt], bF[nt]);
            };

            loadB(bH, t1, 1);    // Eh
            loadB(bM, t2, 0);    // Em
            loadA(t0, 0);        // Rh
            mmaAll(bH);          // hh
            mmaAll(bM);          // hm
            loadB(bL, t2, 1);    // El
            mmaAll(bL);          // hl
            loadA(t0, 1);        // Rm
            mmaAll(bH);          // mh
            mmaAll(bM);          // mm
            loadA(t1, 0);        // Rl
            mmaAll(bH);          // lh
        }
    };

    issue_load(0, 0);
    issue_load(1, 1);
    for (int hc = 0; hc < NHC; hc++) {
        CP_WAIT(1);             // this thread's group hc has landed
        __syncthreads();        // everyone's group hc visible
        compute(hc & 1);
        __syncthreads();        // all warps done reading slot hc&1
        if (hc + 2 < NHC) issue_load(hc + 2, hc & 1);
    }

    // epilogue: exp(2G - ||E||^2) -> g_A
#pragma unroll
    for (int nt = 0; nt < 4; nt++) {
        int col = col0 + wn0 + nt * 8 + (lane & 3) * 2;
        float en0 = __ldg(&g_Enorm[col]);
        float en1 = __ldg(&g_Enorm[col + 1]);
#pragma unroll
        for (int mt = 0; mt < 4; mt++) {
            int r0 = row0 + wm0 + mt * 16 + (lane >> 2);
            float2 v0, v1;
            v0.x = expf(2.0f * acc[mt][nt][0] - en0);
            v0.y = expf(2.0f * acc[mt][nt][1] - en1);
            v1.x = expf(2.0f * acc[mt][nt][2] - en0);
            v1.y = expf(2.0f * acc[mt][nt][3] - en1);
            *(float2*)(g_A + (size_t)r0 * KCB + col)       = v0;
            *(float2*)(g_A + (size_t)(r0 + 8) * KCB + col) = v1;
        }
    }
}

// ---------------------------------------------------------------------------
// One sinkhorn iteration, SINGLE pass over A (tiles kept in registers):
//   c_k = useC ? 1/(K * colsum_prev[k]) : 1
//   r_n = 1/(B * sum_k A[n,k] c_k)
//   colpart[b][k] = sum_{n in block} A[n,k] * r_n   (deterministic partials)
__global__ __launch_bounds__(256) void rowcol_pass(int useC) {
    __shared__ __align__(16) float c_s[KCB];
    __shared__ float wacc[8][KCB];   // per-warp column partials
    const int tid = threadIdx.x, w = tid >> 5, lane = tid & 31;
    const int r0 = blockIdx.x * ROWS;

    for (int k = tid; k < KCB; k += 256)
        c_s[k] = useC ? 1.0f / (1024.0f * g_colsum[k]) : 1.0f;
    __syncthreads();

    const float4* c4 = (const float4*)c_s;
    float4 acc[8];
#pragma unroll
    for (int t = 0; t < 8; t++) acc[t] = make_float4(0.f, 0.f, 0.f, 0.f);

#pragma unroll
    for (int i = 0; i < 8; i++) {        // 8 rows per warp
        int n = r0 + w * 8 + i;
        const float4* a4 = (const float4*)(g_A + (size_t)n * KCB);
        float4 a[8];
        float s = 0.0f;
#pragma unroll
        for (int t = 0; t < 8; t++) {
            a[t] = a4[lane + t * 32];
            float4 c = c4[lane + t * 32];
            s += a[t].x * c.x + a[t].y * c.y + a[t].z * c.z + a[t].w * c.w;
        }
        for (int o = 16; o > 0; o >>= 1) s += __shfl_down_sync(0xffffffffu, s, o);
        s = __shfl_sync(0xffffffffu, s, 0);
        float r = 1.0f / (32768.0f * s);
#pragma unroll
        for (int t = 0; t < 8; t++) {
            acc[t].x += a[t].x * r; acc[t].y += a[t].y * r;
            acc[t].z += a[t].z * r; acc[t].w += a[t].w * r;
        }
    }
    float4* wa4 = (float4*)wacc[w];
#pragma unroll
    for (int t = 0; t < 8; t++) wa4[lane + t * 32] = acc[t];
    __syncthreads();

    for (int k = tid; k < KCB; k += 256) {
        float sum = 0.0f;
#pragma unroll
        for (int ww = 0; ww < 8; ww++) sum += wacc[ww][k];
        g_colpart[(size_t)blockIdx.x * KCB + k] = sum;
    }
}

// deterministic fixed-order reduction of column partials
__global__ void reduce_colsum() {
    int k = blockIdx.x;
    int t = threadIdx.x; // 128
    float s = 0.0f;
    for (int b = t; b < NBLK; b += 128)
        s += g_colpart[(size_t)b * KCB + k];
    __shared__ float sh[128];
    sh[t] = s;
    __syncthreads();
    for (int o = 64; o > 0; o >>= 1) {
        if (t < o) sh[t] += sh[t + o];
        __syncthreads();
    }
    if (t == 0) g_colsum[k] = sh[0];
}

// ---------------------------------------------------------------------------
// Final pass: argmax_k A[n,k]*c3_k (first-index tie-break), gather codeword,
// update out/residual, and write the NEXT level's bf16 3-plane split (fused).
__global__ __launch_bounds__(256) void argmax_gather(const float* __restrict__ E,
                                                     float* __restrict__ out) {
    __shared__ __align__(16) float c_s[KCB];
    const int tid = threadIdx.x;
    const int r0  = blockIdx.x * ROWS;

    for (int k = tid; k < KCB; k += 256)
        c_s[k] = 1.0f / (1024.0f * g_colsum[k]);
    __syncthreads();

    const int w = tid >> 5, lane = tid & 31;
#pragma unroll
    for (int i = 0; i < ROWS / 8; i++) {
        int n = r0 + w * 8 + i;
        const float* a = g_A + (size_t)n * KCB;
        float best = -1e30f;
        int   bi   = 0;
#pragma unroll
        for (int t = 0; t < 8; t++) {
            int kbase = (lane + t * 32) * 4;
            float4 av = *(const float4*)(a + kbase);
            float4 cv = *(const float4*)(c_s + kbase);
            float v;
            v = av.x * cv.x; if (v > best) { best = v; bi = kbase + 0; }
            v = av.y * cv.y; if (v > best) { best = v; bi = kbase + 1; }
            v = av.z * cv.z; if (v > best) { best = v; bi = kbase + 2; }
            v = av.w * cv.w; if (v > best) { best = v; bi = kbase + 3; }
        }
        for (int o = 16; o > 0; o >>= 1) {
            float ov = __shfl_down_sync(0xffffffffu, best, o);
            int   oi = __shfl_down_sync(0xffffffffu, bi, o);
            if (ov > best || (ov == best && oi < bi)) { best = ov; bi = oi; }
        }
        bi = __shfl_sync(0xffffffffu, bi, 0);

        // each lane owns 16 contiguous dims -> coalesced fp32 & bf16 traffic
        const int d0 = lane * 16;
        const float4* e4  = (const float4*)(E + (size_t)bi * DDIM + d0);
        float4* rp4 = (float4*)(g_resid + (size_t)n * DDIM + d0);
        float4* op4 = (float4*)(out     + (size_t)n * DDIM + d0);
        uint32_t hw[8], mw[8], lw[8];
#pragma unroll
        for (int j = 0; j < 4; j++) {
            float4 ev = e4[j];
            float4 rv = rp4[j];
            rv.x -= ev.x; rv.y -= ev.y; rv.z -= ev.z; rv.w -= ev.w;
            rp4[j] = rv;
            float4 ov = op4[j];
            ov.x += ev.x; ov.y += ev.y; ov.z += ev.z; ov.w += ev.w;
            op4[j] = ov;
            __nv_bfloat16 h0, m0, l0, h1, m1, l1, h2, m2, l2, h3, m3, l3;
            split3(rv.x, h0, m0, l0); split3(rv.y, h1, m1, l1);
            split3(rv.z, h2, m2, l2); split3(rv.w, h3, m3, l3);
            __nv_bfloat162 hp0 = __halves2bfloat162(h0, h1), hp1 = __halves2bfloat162(h2, h3);
            __nv_bfloat162 mp0 = __halves2bfloat162(m0, m1), mp1 = __halves2bfloat162(m2, m3);
            __nv_bfloat162 lp0 = __halves2bfloat162(l0, l1), lp1 = __halves2bfloat162(l2, l3);
            hw[j * 2 + 0] = *(uint32_t*)&hp0; hw[j * 2 + 1] = *(uint32_t*)&hp1;
            mw[j * 2 + 0] = *(uint32_t*)&mp0; mw[j * 2 + 1] = *(uint32_t*)&mp1;
            lw[j * 2 + 0] = *(uint32_t*)&lp0; lw[j * 2 + 1] = *(uint32_t*)&lp1;
        }
        uint4* hdst = (uint4*)(g_Rs[0] + (size_t)n * DDIM + d0);
        uint4* mdst = (uint4*)(g_Rs[1] + (size_t)n * DDIM + d0);
        uint4* ldst = (uint4*)(g_Rs[2] + (size_t)n * DDIM + d0);
        hdst[0] = make_uint4(hw[0], hw[1], hw[2], hw[3]);
        hdst[1] = make_uint4(hw[4], hw[5], hw[6], hw[7]);
        mdst[0] = make_uint4(mw[0], mw[1], mw[2], mw[3]);
        mdst[1] = make_uint4(mw[4], mw[5], mw[6], mw[7]);
        ldst[0] = make_uint4(lw[0], lw[1], lw[2], lw[3]);
        ldst[1] = make_uint4(lw[4], lw[5], lw[6], lw[7]);
    }
}

// ---------------------------------------------------------------------------
extern "C" void kernel_launch(void* const* d_in, const int* in_sizes, int n_in,
                              void* d_out, int out_size) {
    const float* x         = (const float*)d_in[0];
    const float* codebooks = (const float*)d_in[1];
    // d_in[2] = sigma: dead in forward (straight-through cancels y_soft exactly)
    float* out = (float*)d_out;

    static int smem_set = 0;
    if (!smem_set) {
        cudaFuncSetAttribute(gemm_hmma,
                             cudaFuncAttributeMaxDynamicSharedMemorySize,
                             SMEM_GEMM);
        smem_set = 1;
    }

    init_kernel<<<(NTOK * DDIM + 255) / 256, 256>>>(x, out);
    split_E_kernel<<<(NQ * KCB * DDIM + 255) / 256, 256>>>(codebooks);

    for (int lvl = 0; lvl < NQ; lvl++) {
        const float* E = codebooks + (size_t)lvl * KCB * DDIM;

        enorm_kernel<<<KCB, 128>>>(E);

        gemm_hmma<<<dim3(KCB / 128, NTOK / 128), 256, SMEM_GEMM>>>(lvl);

        rowcol_pass<<<NBLK, 256>>>(0);
        reduce_colsum<<<KCB, 128>>>();
        rowcol_pass<<<NBLK, 256>>>(1);
        reduce_colsum<<<KCB, 128>>>();
        rowcol_pass<<<NBLK, 256>>>(1);
        reduce_colsum<<<KCB, 128>>>();

        argmax_gather<<<NBLK, 256>>>(E, out);
    }
}

// round 14
// speedup vs baseline: 1.8896x; 1.0570x over previous
#include <cuda_runtime.h>
#include <cuda_bf16.h>
#include <math.h>
#include <stdint.h>

// Problem constants (fixed by the dataset)
#define NTOK 32768
#define DDIM 512
#define KCB  1024
#define NQ   4

#define ROWS 64                  // rows per block in sinkhorn passes
#define NBLK (NTOK / ROWS)       // 512 blocks

// -------- scratch (static __device__ globals; no allocation allowed) --------
__device__ float g_A[(size_t)NTOK * KCB];      // exp(2G - ||E||^2), 134 MB
__device__ float g_resid[(size_t)NTOK * DDIM]; // running residual, 64 MB
__device__ float g_Enorm[NQ * KCB];
__device__ float g_colsum[KCB];
__device__ float g_colpart[(size_t)NBLK * KCB];
// bf16 3-way splits (hi/mid/lo, all normal-range) for 6-product fp32 emulation
__device__ __align__(256) __nv_bfloat16 g_Rs[3][(size_t)NTOK * DDIM];
__device__ __align__(256) __nv_bfloat16 g_Es[3][(size_t)NQ * KCB * DDIM];

// ---------------------------------------------------------------------------
__device__ __forceinline__ uint32_t smem_u32(const void* p) {
    uint32_t a;
    asm("{ .reg .u64 t; cvta.to.shared.u64 t, %1; cvt.u32.u64 %0, t; }"
        : "=r"(a) : "l"(p));
    return a;
}
__device__ __forceinline__ void cp16(uint32_t dst, const void* src) {
    asm volatile("cp.async.cg.shared.global [%0], [%1], 16;"
                 :: "r"(dst), "l"(src));
}
#define CP_COMMIT() asm volatile("cp.async.commit_group;")
#define CP_WAIT(n)  asm volatile("cp.async.wait_group %0;" :: "n"(n))

__device__ __forceinline__ void ldmx4(uint32_t* r, uint32_t addr) {
    asm volatile("ldmatrix.sync.aligned.m8n8.x4.shared.b16 {%0,%1,%2,%3}, [%4];"
                 : "=r"(r[0]), "=r"(r[1]), "=r"(r[2]), "=r"(r[3]) : "r"(addr));
}
__device__ __forceinline__ void mma16816bf(float* c, const uint32_t* a,
                                           const uint32_t* b) {
    asm volatile(
        "mma.sync.aligned.m16n8k16.row.col.f32.bf16.bf16.f32 "
        "{%0,%1,%2,%3}, {%4,%5,%6,%7}, {%8,%9}, {%0,%1,%2,%3};"
        : "+f"(c[0]), "+f"(c[1]), "+f"(c[2]), "+f"(c[3])
        : "r"(a[0]), "r"(a[1]), "r"(a[2]), "r"(a[3]), "r"(b[0]), "r"(b[1]));
}

// 3-way bf16 split (remainders exact in fp32; bf16 range = fp32, no subnormals)
__device__ __forceinline__ void split3(float a, __nv_bfloat16& h,
                                       __nv_bfloat16& m, __nv_bfloat16& l) {
    h = __float2bfloat16(a);
    float r1 = a - __bfloat162float(h);
    m = __float2bfloat16(r1);
    float r2 = r1 - __bfloat162float(m);
    l = __float2bfloat16(r2);
}

// ---------------------------------------------------------------------------
// init: residual = x, level-0 split of x (fused). out untouched: the final
// argmax_gather writes every element of out directly (out = x - resid_final).
__global__ void init_kernel(const float* __restrict__ x) {
    int i = blockIdx.x * blockDim.x + threadIdx.x;
    if (i < NTOK * DDIM) {
        float a = x[i];
        g_resid[i] = a;
        __nv_bfloat16 h, m, l;
        split3(a, h, m, l);
        g_Rs[0][i] = h;
        g_Rs[1][i] = m;
        g_Rs[2][i] = l;
    }
}

// split all codebooks once per launch
__global__ void split_E_kernel(const float* __restrict__ codebooks) {
    int i = blockIdx.x * blockDim.x + threadIdx.x;
    if (i < NQ * KCB * DDIM) {
        __nv_bfloat16 h, m, l;
        split3(codebooks[i], h, m, l);
        g_Es[0][i] = h;
        g_Es[1][i] = m;
        g_Es[2][i] = l;
    }
}

// ---------------------------------------------------------------------------
// ||E_k||^2 for ALL levels in one launch (fp32, deterministic order)
__global__ void enorm_kernel(const float* __restrict__ codebooks) {
    int k = blockIdx.x;                  // 0 .. NQ*KCB-1
    int t = threadIdx.x;                 // 128
    float s = 0.0f;
    const float* row = codebooks + (size_t)k * DDIM;
    for (int d = t; d < DDIM; d += 128) { float v = row[d]; s += v * v; }
    __shared__ float sh[128];
    sh[t] = s;
    __syncthreads();
    for (int o = 64; o > 0; o >>= 1) {
        if (t < o) sh[t] += sh[t + o];
        __syncthreads();
    }
    if (t == 0) g_Enorm[k] = sh[0];
}

// ---------------------------------------------------------------------------
// HMMA GEMM: G = sum of 6 bf16 plane-products (hh,hm,mh,mm,hl,lh).
// Stage = one physical k32 slice holding ALL 6 planes as 3 pair-tiles
// (128 rows x 128 B, SW swizzle): T0=(Rh|Rm) T1=(Rl|Eh) T2=(Em|El).
// 16 stages, 2-stage cp.async ring. Epilogue fused: g_A = exp(2G - ||E||^2).
#define TILE_B  16384                   // 128 rows * 128 B
#define BUF_B   (3 * TILE_B)            // 48 KB per stage
#define NSTAGE  2
#define NHC     16                      // 512 / 32 half-chunks
#define SMEM_GEMM (NSTAGE * BUF_B)      // 96 KB

__global__ __launch_bounds__(256, 2) void gemm_hmma(int lvl) {
    extern __shared__ char sm[];
    const uint32_t sbase = smem_u32(sm);
    const int tid  = threadIdx.x;
    const int wid  = tid >> 5;
    const int lane = tid & 31;
    const int row0 = blockIdx.y * 128;  // token tile
    const int col0 = blockIdx.x * 128;  // codebook tile
    const size_t eoff = (size_t)lvl * KCB * DDIM;

    const int wm0 = (wid & 1) * 64;
    const int wn0 = (wid >> 1) * 32;

    float acc[4][4][4];
#pragma unroll
    for (int mt = 0; mt < 4; mt++)
#pragma unroll
        for (int nt = 0; nt < 4; nt++)
#pragma unroll
            for (int e = 0; e < 4; e++) acc[mt][nt][e] = 0.0f;

    // plane table: 0..2 = Rh,Rm,Rl (token rows); 3..5 = Eh,Em,El (codebook rows)
    const __nv_bfloat16* plane[6] = {
        g_Rs[0], g_Rs[1], g_Rs[2],
        g_Es[0] + eoff, g_Es[1] + eoff, g_Es[2] + eoff
    };

    // stage hc: pair-tile t holds planes (2t | 2t+1); left half = 4x16B units
    auto issue_load = [&](int hc, int slot) {
        const int koff = hc * 32;
        const uint32_t dbase = sbase + slot * BUF_B;
#pragma unroll
        for (int i = 0; i < 12; i++) {
            int v   = tid + i * 256;
            int t   = v >> 10;           // tile 0..2
            int rr  = (v >> 3) & 127;    // row
            int c16 = v & 7;             // 16B unit
            int p   = t * 2 + (c16 >> 2);
            int rb  = (p >= 3) ? col0 : row0;
            const __nv_bfloat16* src =
                plane[p] + (size_t)(rb + rr) * DDIM + koff + (c16 & 3) * 8;
            uint32_t dst = dbase + t * TILE_B + rr * 128 + ((c16 ^ (rr & 7)) << 4);
            cp16(dst, src);
        }
        CP_COMMIT();
    };

    auto compute = [&](int slot) {
        const uint32_t t0 = sbase + slot * BUF_B;
        const uint32_t t1 = t0 + TILE_B;
        const uint32_t t2 = t1 + TILE_B;
#pragma unroll
        for (int ks = 0; ks < 2; ks++) {
            const int au = ks * 2 + (lane >> 4);        // A unit within half
            const int bu = ks * 2 + ((lane >> 3) & 1);  // B unit within half

            uint32_t aF[4][4], bH[4][2], bM[4][2], bL[4][2];

            // B fragment loader: tile + half (0 = units 0..3, 1 = units 4..7)
            auto loadB = [&](uint32_t (*dst)[2], uint32_t tile, int half) {
#pragma unroll
                for (int bt = 0; bt < 2; bt++) {
                    int nrow = wn0 + bt * 16 + (lane & 7) + ((lane >> 4) << 3);
                    int u = half * 4 + bu;
                    uint32_t r[4];
                    ldmx4(r, tile + nrow * 128 + ((u ^ (nrow & 7)) << 4));
                    dst[bt * 2 + 0][0] = r[0]; dst[bt * 2 + 0][1] = r[1];
                    dst[bt * 2 + 1][0] = r[2]; dst[bt * 2 + 1][1] = r[3];
                }
            };
            auto loadA = [&](uint32_t tile, int half) {
#pragma unroll
                for (int mt = 0; mt < 4; mt++) {
                    int row = wm0 + mt * 16 + (lane & 15);
                    int u = half * 4 + au;
                    ldmx4(aF[mt], tile + row * 128 + ((u ^ (row & 7)) << 4));
                }
            };
            auto mmaAll = [&](uint32_t (*bF)[2]) {
#pragma unroll
                for (int mt = 0; mt < 4; mt++)
#pragma unroll
                    for (int nt = 0; nt < 4; nt++)
                        mma16816bf(acc[mt][nt], aF[mt], bF[nt]);
            };

            loadB(bH, t1, 1);    // Eh
            loadB(bM, t2, 0);    // Em
            loadA(t0, 0);        // Rh
            mmaAll(bH);          // hh
            mmaAll(bM);          // hm
            loadB(bL, t2, 1);    // El
            mmaAll(bL);          // hl
            loadA(t0, 1);        // Rm
            mmaAll(bH);          // mh
            mmaAll(bM);          // mm
            loadA(t1, 0);        // Rl
            mmaAll(bH);          // lh
        }
    };

    issue_load(0, 0);
    issue_load(1, 1);
    for (int hc = 0; hc < NHC; hc++) {
        CP_WAIT(1);             // this thread's group hc has landed
        __syncthreads();        // everyone's group hc visible
        compute(hc & 1);
        __syncthreads();        // all warps done reading slot hc&1
        if (hc + 2 < NHC) issue_load(hc + 2, hc & 1);
    }

    // epilogue: exp(2G - ||E||^2) -> g_A
    const float* en = g_Enorm + lvl * KCB;
#pragma unroll
    for (int nt = 0; nt < 4; nt++) {
        int col = col0 + wn0 + nt * 8 + (lane & 3) * 2;
        float en0 = __ldg(&en[col]);
        float en1 = __ldg(&en[col + 1]);
#pragma unroll
        for (int mt = 0; mt < 4; mt++) {
            int r0 = row0 + wm0 + mt * 16 + (lane >> 2);
            float2 v0, v1;
            v0.x = expf(2.0f * acc[mt][nt][0] - en0);
            v0.y = expf(2.0f * acc[mt][nt][1] - en1);
            v1.x = expf(2.0f * acc[mt][nt][2] - en0);
            v1.y = expf(2.0f * acc[mt][nt][3] - en1);
            *(float2*)(g_A + (size_t)r0 * KCB + col)       = v0;
            *(float2*)(g_A + (size_t)(r0 + 8) * KCB + col) = v1;
        }
    }
}

// ---------------------------------------------------------------------------
// One sinkhorn iteration, SINGLE pass over A (tiles kept in registers):
//   c_k = useC ? 1/(K * colsum_prev[k]) : 1
//   r_n = 1/(B * sum_k A[n,k] c_k)
//   colpart[b][k] = sum_{n in block} A[n,k] * r_n   (deterministic partials)
__global__ __launch_bounds__(256) void rowcol_pass(int useC) {
    __shared__ __align__(16) float c_s[KCB];
    __shared__ float wacc[8][KCB];   // per-warp column partials
    const int tid = threadIdx.x, w = tid >> 5, lane = tid & 31;
    const int r0 = blockIdx.x * ROWS;

    for (int k = tid; k < KCB; k += 256)
        c_s[k] = useC ? 1.0f / (1024.0f * g_colsum[k]) : 1.0f;
    __syncthreads();

    const float4* c4 = (const float4*)c_s;
    float4 acc[8];
#pragma unroll
    for (int t = 0; t < 8; t++) acc[t] = make_float4(0.f, 0.f, 0.f, 0.f);

#pragma unroll
    for (int i = 0; i < 8; i++) {        // 8 rows per warp
        int n = r0 + w * 8 + i;
        const float4* a4 = (const float4*)(g_A + (size_t)n * KCB);
        float4 a[8];
        float s = 0.0f;
#pragma unroll
        for (int t = 0; t < 8; t++) {
            a[t] = a4[lane + t * 32];
            float4 c = c4[lane + t * 32];
            s += a[t].x * c.x + a[t].y * c.y + a[t].z * c.z + a[t].w * c.w;
        }
        for (int o = 16; o > 0; o >>= 1) s += __shfl_down_sync(0xffffffffu, s, o);
        s = __shfl_sync(0xffffffffu, s, 0);
        float r = 1.0f / (32768.0f * s);
#pragma unroll
        for (int t = 0; t < 8; t++) {
            acc[t].x += a[t].x * r; acc[t].y += a[t].y * r;
            acc[t].z += a[t].z * r; acc[t].w += a[t].w * r;
        }
    }
    float4* wa4 = (float4*)wacc[w];
#pragma unroll
    for (int t = 0; t < 8; t++) wa4[lane + t * 32] = acc[t];
    __syncthreads();

    for (int k = tid; k < KCB; k += 256) {
        float sum = 0.0f;
#pragma unroll
        for (int ww = 0; ww < 8; ww++) sum += wacc[ww][k];
        g_colpart[(size_t)blockIdx.x * KCB + k] = sum;
    }
}

// deterministic fixed-order reduction of column partials
__global__ void reduce_colsum() {
    int k = blockIdx.x;
    int t = threadIdx.x; // 128
    float s = 0.0f;
    for (int b = t; b < NBLK; b += 128)
        s += g_colpart[(size_t)b * KCB + k];
    __shared__ float sh[128];
    sh[t] = s;
    __syncthreads();
    for (int o = 64; o > 0; o >>= 1) {
        if (t < o) sh[t] += sh[t + o];
        __syncthreads();
    }
    if (t == 0) g_colsum[k] = sh[0];
}

// ---------------------------------------------------------------------------
// Final pass: argmax_k A[n,k]*c3_k (first-index tie-break), gather codeword.
//   last == 0: resid -= E[idx]; write next level's bf16 3-plane split.
//   last == 1: out = x - (resid - E[idx]); no resid/split writes (dead).
__global__ __launch_bounds__(256) void argmax_gather(const float* __restrict__ E,
                                                     const float* __restrict__ x,
                                                     float* __restrict__ out,
                                                     int last) {
    __shared__ __align__(16) float c_s[KCB];
    const int tid = threadIdx.x;
    const int r0  = blockIdx.x * ROWS;

    for (int k = tid; k < KCB; k += 256)
        c_s[k] = 1.0f / (1024.0f * g_colsum[k]);
    __syncthreads();

    const int w = tid >> 5, lane = tid & 31;
#pragma unroll
    for (int i = 0; i < ROWS / 8; i++) {
        int n = r0 + w * 8 + i;
        const float* a = g_A + (size_t)n * KCB;
        float best = -1e30f;
        int   bi   = 0;
#pragma unroll
        for (int t = 0; t < 8; t++) {
            int kbase = (lane + t * 32) * 4;
            float4 av = *(const float4*)(a + kbase);
            float4 cv = *(const float4*)(c_s + kbase);
            float v;
            v = av.x * cv.x; if (v > best) { best = v; bi = kbase + 0; }
            v = av.y * cv.y; if (v > best) { best = v; bi = kbase + 1; }
            v = av.z * cv.z; if (v > best) { best = v; bi = kbase + 2; }
            v = av.w * cv.w; if (v > best) { best = v; bi = kbase + 3; }
        }
        for (int o = 16; o > 0; o >>= 1) {
            float ov = __shfl_down_sync(0xffffffffu, best, o);
            int   oi = __shfl_down_sync(0xffffffffu, bi, o);
            if (ov > best || (ov == best && oi < bi)) { best = ov; bi = oi; }
        }
        bi = __shfl_sync(0xffffffffu, bi, 0);

        // each lane owns 16 contiguous dims -> coalesced fp32 & bf16 traffic
        const int d0 = lane * 16;
        const float4* e4  = (const float4*)(E + (size_t)bi * DDIM + d0);
        float4* rp4 = (float4*)(g_resid + (size_t)n * DDIM + d0);

        if (last) {
            const float4* x4 = (const float4*)(x + (size_t)n * DDIM + d0);
            float4* o4 = (float4*)(out + (size_t)n * DDIM + d0);
#pragma unroll
            for (int j = 0; j < 4; j++) {
                float4 ev = e4[j];
                float4 rv = rp4[j];
                float4 xv = x4[j];
                float4 ov;
                ov.x = xv.x - (rv.x - ev.x);
                ov.y = xv.y - (rv.y - ev.y);
                ov.z = xv.z - (rv.z - ev.z);
                ov.w = xv.w - (rv.w - ev.w);
                o4[j] = ov;
            }
        } else {
            uint32_t hw[8], mw[8], lw[8];
#pragma unroll
            for (int j = 0; j < 4; j++) {
                float4 ev = e4[j];
                float4 rv = rp4[j];
                rv.x -= ev.x; rv.y -= ev.y; rv.z -= ev.z; rv.w -= ev.w;
                rp4[j] = rv;
                __nv_bfloat16 h0, m0, l0, h1, m1, l1, h2, m2, l2, h3, m3, l3;
                split3(rv.x, h0, m0, l0); split3(rv.y, h1, m1, l1);
                split3(rv.z, h2, m2, l2); split3(rv.w, h3, m3, l3);
                __nv_bfloat162 hp0 = __halves2bfloat162(h0, h1), hp1 = __halves2bfloat162(h2, h3);
                __nv_bfloat162 mp0 = __halves2bfloat162(m0, m1), mp1 = __halves2bfloat162(m2, m3);
                __nv_bfloat162 lp0 = __halves2bfloat162(l0, l1), lp1 = __halves2bfloat162(l2, l3);
                hw[j * 2 + 0] = *(uint32_t*)&hp0; hw[j * 2 + 1] = *(uint32_t*)&hp1;
                mw[j * 2 + 0] = *(uint32_t*)&mp0; mw[j * 2 + 1] = *(uint32_t*)&mp1;
                lw[j * 2 + 0] = *(uint32_t*)&lp0; lw[j * 2 + 1] = *(uint32_t*)&lp1;
            }
            uint4* hdst = (uint4*)(g_Rs[0] + (size_t)n * DDIM + d0);
            uint4* mdst = (uint4*)(g_Rs[1] + (size_t)n * DDIM + d0);
            uint4* ldst = (uint4*)(g_Rs[2] + (size_t)n * DDIM + d0);
            hdst[0] = make_uint4(hw[0], hw[1], hw[2], hw[3]);
            hdst[1] = make_uint4(hw[4], hw[5], hw[6], hw[7]);
            mdst[0] = make_uint4(mw[0], mw[1], mw[2], mw[3]);
            mdst[1] = make_uint4(mw[4], mw[5], mw[6], mw[7]);
            ldst[0] = make_uint4(lw[0], lw[1], lw[2], lw[3]);
            ldst[1] = make_uint4(lw[4], lw[5], lw[6], lw[7]);
        }
    }
}

// ---------------------------------------------------------------------------
extern "C" void kernel_launch(void* const* d_in, const int* in_sizes, int n_in,
                              void* d_out, int out_size) {
    const float* x         = (const float*)d_in[0];
    const float* codebooks = (const float*)d_in[1];
    // d_in[2] = sigma: dead in forward (straight-through cancels y_soft exactly)
    float* out = (float*)d_out;

    static int smem_set = 0;
    if (!smem_set) {
        cudaFuncSetAttribute(gemm_hmma,
                             cudaFuncAttributeMaxDynamicSharedMemorySize,
                             SMEM_GEMM);
        smem_set = 1;
    }

    init_kernel<<<(NTOK * DDIM + 255) / 256, 256>>>(x);
    split_E_kernel<<<(NQ * KCB * DDIM + 255) / 256, 256>>>(codebooks);
    enorm_kernel<<<NQ * KCB, 128>>>(codebooks);

    for (int lvl = 0; lvl < NQ; lvl++) {
        const float* E = codebooks + (size_t)lvl * KCB * DDIM;

        gemm_hmma<<<dim3(KCB / 128, NTOK / 128), 256, SMEM_GEMM>>>(lvl);

        rowcol_pass<<<NBLK, 256>>>(0);
        reduce_colsum<<<KCB, 128>>>();
        rowcol_pass<<<NBLK, 256>>>(1);
        reduce_colsum<<<KCB, 128>>>();
        rowcol_pass<<<NBLK, 256>>>(1);
        reduce_colsum<<<KCB, 128>>>();

        argmax_gather<<<NBLK, 256>>>(E, x, out, lvl == NQ - 1 ? 1 : 0);
    }
}

// round 16
// speedup vs baseline: 1.9247x; 1.0186x over previous
#include <cuda_runtime.h>
#include <cuda_bf16.h>
#include <math.h>
#include <stdint.h>

// Problem constants (fixed by the dataset)
#define NTOK 32768
#define DDIM 512
#define KCB  1024
#define NQ   4

#define ROWS 64                  // rows per block in sinkhorn passes
#define NBLK (NTOK / ROWS)       // 512 blocks

// -------- scratch (static __device__ globals; no allocation allowed) --------
__device__ float g_A[(size_t)NTOK * KCB];      // exp(2G - ||E||^2), 134 MB
__device__ float g_resid[(size_t)NTOK * DDIM]; // running residual, 64 MB
__device__ float g_Enorm[NQ * KCB];
__device__ float g_colsum[KCB];
__device__ float g_colpart[(size_t)NBLK * KCB];
// bf16 3-way splits (hi/mid/lo, all normal-range) for 6-product fp32 emulation
__device__ __align__(256) __nv_bfloat16 g_Rs[3][(size_t)NTOK * DDIM];
__device__ __align__(256) __nv_bfloat16 g_Es[3][(size_t)NQ * KCB * DDIM];

// ---------------------------------------------------------------------------
__device__ __forceinline__ uint32_t smem_u32(const void* p) {
    uint32_t a;
    asm("{ .reg .u64 t; cvta.to.shared.u64 t, %1; cvt.u32.u64 %0, t; }"
        : "=r"(a) : "l"(p));
    return a;
}
__device__ __forceinline__ void cp16(uint32_t dst, const void* src) {
    asm volatile("cp.async.cg.shared.global [%0], [%1], 16;"
                 :: "r"(dst), "l"(src));
}
#define CP_COMMIT() asm volatile("cp.async.commit_group;")
#define CP_WAIT(n)  asm volatile("cp.async.wait_group %0;" :: "n"(n))

__device__ __forceinline__ void ldmx4(uint32_t* r, uint32_t addr) {
    asm volatile("ldmatrix.sync.aligned.m8n8.x4.shared.b16 {%0,%1,%2,%3}, [%4];"
                 : "=r"(r[0]), "=r"(r[1]), "=r"(r[2]), "=r"(r[3]) : "r"(addr));
}
__device__ __forceinline__ void mma16816bf(float* c, const uint32_t* a,
                                           const uint32_t* b) {
    asm volatile(
        "mma.sync.aligned.m16n8k16.row.col.f32.bf16.bf16.f32 "
        "{%0,%1,%2,%3}, {%4,%5,%6,%7}, {%8,%9}, {%0,%1,%2,%3};"
        : "+f"(c[0]), "+f"(c[1]), "+f"(c[2]), "+f"(c[3])
        : "r"(a[0]), "r"(a[1]), "r"(a[2]), "r"(a[3]), "r"(b[0]), "r"(b[1]));
}

// 3-way bf16 split (remainders exact in fp32; bf16 range = fp32, no subnormals)
__device__ __forceinline__ void split3(float a, __nv_bfloat16& h,
                                       __nv_bfloat16& m, __nv_bfloat16& l) {
    h = __float2bfloat16(a);
    float r1 = a - __bfloat162float(h);
    m = __float2bfloat16(r1);
    float r2 = r1 - __bfloat162float(m);
    l = __float2bfloat16(r2);
}

// ---------------------------------------------------------------------------
// init: residual = x, level-0 split of x (fused). out untouched: the final
// argmax_gather writes every element of out directly (out = x - resid_final).
__global__ void init_kernel(const float* __restrict__ x) {
    int i = blockIdx.x * blockDim.x + threadIdx.x;
    if (i < NTOK * DDIM) {
        float a = x[i];
        g_resid[i] = a;
        __nv_bfloat16 h, m, l;
        split3(a, h, m, l);
        g_Rs[0][i] = h;
        g_Rs[1][i] = m;
        g_Rs[2][i] = l;
    }
}

// split all codebooks once per launch
__global__ void split_E_kernel(const float* __restrict__ codebooks) {
    int i = blockIdx.x * blockDim.x + threadIdx.x;
    if (i < NQ * KCB * DDIM) {
        __nv_bfloat16 h, m, l;
        split3(codebooks[i], h, m, l);
        g_Es[0][i] = h;
        g_Es[1][i] = m;
        g_Es[2][i] = l;
    }
}

// ---------------------------------------------------------------------------
// ||E_k||^2 for ALL levels in one launch (fp32, deterministic order)
__global__ void enorm_kernel(const float* __restrict__ codebooks) {
    int k = blockIdx.x;                  // 0 .. NQ*KCB-1
    int t = threadIdx.x;                 // 128
    float s = 0.0f;
    const float* row = codebooks + (size_t)k * DDIM;
    for (int d = t; d < DDIM; d += 128) { float v = row[d]; s += v * v; }
    __shared__ float sh[128];
    sh[t] = s;
    __syncthreads();
    for (int o = 64; o > 0; o >>= 1) {
        if (t < o) sh[t] += sh[t + o];
        __syncthreads();
    }
    if (t == 0) g_Enorm[k] = sh[0];
}

// ---------------------------------------------------------------------------
// HMMA GEMM: G = sum of 6 bf16 plane-products (hh,hm,mh,mm,hl,lh).
// Stage = one physical k32 slice holding ALL 6 planes as 3 pair-tiles
// (128 rows x 128 B, SW swizzle): T0=(Rh|Rm) T1=(Rl|Eh) T2=(Em|El).
// 16 stages, 2-stage cp.async ring, ONE __syncthreads per stage:
//   iter hc: wait(0) [group hc landed]; sync [compute(hc-1) done everywhere];
//            issue(hc+1 -> slot (hc+1)&1 == (hc-1)&1, freed by that compute];
//            compute(hc).
// Epilogue fused: g_A = exp(2G - ||E||^2).
#define TILE_B  16384                   // 128 rows * 128 B
#define BUF_B   (3 * TILE_B)            // 48 KB per stage
#define NSTAGE  2
#define NHC     16                      // 512 / 32 half-chunks
#define SMEM_GEMM (NSTAGE * BUF_B)      // 96 KB

__global__ __launch_bounds__(256, 2) void gemm_hmma(int lvl) {
    extern __shared__ char sm[];
    const uint32_t sbase = smem_u32(sm);
    const int tid  = threadIdx.x;
    const int wid  = tid >> 5;
    const int lane = tid & 31;
    const int row0 = blockIdx.y * 128;  // token tile
    const int col0 = blockIdx.x * 128;  // codebook tile
    const size_t eoff = (size_t)lvl * KCB * DDIM;

    const int wm0 = (wid & 1) * 64;
    const int wn0 = (wid >> 1) * 32;

    float acc[4][4][4];
#pragma unroll
    for (int mt = 0; mt < 4; mt++)
#pragma unroll
        for (int nt = 0; nt < 4; nt++)
#pragma unroll
            for (int e = 0; e < 4; e++) acc[mt][nt][e] = 0.0f;

    // plane table: 0..2 = Rh,Rm,Rl (token rows); 3..5 = Eh,Em,El (codebook rows)
    const __nv_bfloat16* plane[6] = {
        g_Rs[0], g_Rs[1], g_Rs[2],
        g_Es[0] + eoff, g_Es[1] + eoff, g_Es[2] + eoff
    };

    // stage hc: pair-tile t holds planes (2t | 2t+1); left half = 4x16B units
    auto issue_load = [&](int hc, int slot) {
        const int koff = hc * 32;
        const uint32_t dbase = sbase + slot * BUF_B;
#pragma unroll
        for (int i = 0; i < 12; i++) {
            int v   = tid + i * 256;
            int t   = v >> 10;           // tile 0..2
            int rr  = (v >> 3) & 127;    // row
            int c16 = v & 7;             // 16B unit
            int p   = t * 2 + (c16 >> 2);
            int rb  = (p >= 3) ? col0 : row0;
            const __nv_bfloat16* src =
                plane[p] + (size_t)(rb + rr) * DDIM + koff + (c16 & 3) * 8;
            uint32_t dst = dbase + t * TILE_B + rr * 128 + ((c16 ^ (rr & 7)) << 4);
            cp16(dst, src);
        }
        CP_COMMIT();
    };

    auto compute = [&](int slot) {
        const uint32_t t0 = sbase + slot * BUF_B;
        const uint32_t t1 = t0 + TILE_B;
        const uint32_t t2 = t1 + TILE_B;
#pragma unroll
        for (int ks = 0; ks < 2; ks++) {
            const int au = ks * 2 + (lane >> 4);        // A unit within half
            const int bu = ks * 2 + ((lane >> 3) & 1);  // B unit within half

            uint32_t aF[4][4], bH[4][2], bM[4][2], bL[4][2];

            // B fragment loader: tile + half (0 = units 0..3, 1 = units 4..7)
            auto loadB = [&](uint32_t (*dst)[2], uint32_t tile, int half) {
#pragma unroll
                for (int bt = 0; bt < 2; bt++) {
                    int nrow = wn0 + bt * 16 + (lane & 7) + ((lane >> 4) << 3);
                    int u = half * 4 + bu;
                    uint32_t r[4];
                    ldmx4(r, tile + nrow * 128 + ((u ^ (nrow & 7)) << 4));
                    dst[bt * 2 + 0][0] = r[0]; dst[bt * 2 + 0][1] = r[1];
                    dst[bt * 2 + 1][0] = r[2]; dst[bt * 2 + 1][1] = r[3];
                }
            };
            auto loadA = [&](uint32_t tile, int half) {
#pragma unroll
                for (int mt = 0; mt < 4; mt++) {
                    int row = wm0 + mt * 16 + (lane & 15);
                    int u = half * 4 + au;
                    ldmx4(aF[mt], tile + row * 128 + ((u ^ (row & 7)) << 4));
                }
            };
            auto mmaAll = [&](uint32_t (*bF)[2]) {
#pragma unroll
                for (int mt = 0; mt < 4; mt++)
#pragma unroll
                    for (int nt = 0; nt < 4; nt++)
                        mma16816bf(acc[mt][nt], aF[mt], bF[nt]);
            };

            loadB(bH, t1, 1);    // Eh
            loadB(bM, t2, 0);    // Em
            loadA(t0, 0);        // Rh
            mmaAll(bH);          // hh
            mmaAll(bM);          // hm
            loadB(bL, t2, 1);    // El
            mmaAll(bL);          // hl
            loadA(t0, 1);        // Rm
            mmaAll(bH);          // mh
            mmaAll(bM);          // mm
            loadA(t1, 0);        // Rl
            mmaAll(bH);          // lh
        }
    };

    issue_load(0, 0);
    for (int hc = 0; hc < NHC; hc++) {
        CP_WAIT(0);             // only group hc is outstanding -> it landed
        __syncthreads();        // data visible to all; compute(hc-1) done
        if (hc + 1 < NHC) issue_load(hc + 1, (hc + 1) & 1);
        compute(hc & 1);
    }

    // epilogue: exp(2G - ||E||^2) -> g_A
    const float* en = g_Enorm + lvl * KCB;
#pragma unroll
    for (int nt = 0; nt < 4; nt++) {
        int col = col0 + wn0 + nt * 8 + (lane & 3) * 2;
        float en0 = __ldg(&en[col]);
        float en1 = __ldg(&en[col + 1]);
#pragma unroll
        for (int mt = 0; mt < 4; mt++) {
            int r0 = row0 + wm0 + mt * 16 + (lane >> 2);
            float2 v0, v1;
            v0.x = expf(2.0f * acc[mt][nt][0] - en0);
            v0.y = expf(2.0f * acc[mt][nt][1] - en1);
            v1.x = expf(2.0f * acc[mt][nt][2] - en0);
            v1.y = expf(2.0f * acc[mt][nt][3] - en1);
            *(float2*)(g_A + (size_t)r0 * KCB + col)       = v0;
            *(float2*)(g_A + (size_t)(r0 + 8) * KCB + col) = v1;
        }
    }
}

// ---------------------------------------------------------------------------
// One sinkhorn iteration, SINGLE pass over A (tiles kept in registers):
//   c_k = useC ? 1/(K * colsum_prev[k]) : 1
//   r_n = 1/(B * sum_k A[n,k] c_k)
//   colpart[b][k] = sum_{n in block} A[n,k] * r_n   (deterministic partials)
__global__ __launch_bounds__(256) void rowcol_pass(int useC) {
    __shared__ __align__(16) float c_s[KCB];
    __shared__ float wacc[8][KCB];   // per-warp column partials
    const int tid = threadIdx.x, w = tid >> 5, lane = tid & 31;
    const int r0 = blockIdx.x * ROWS;

    for (int k = tid; k < KCB; k += 256)
        c_s[k] = useC ? 1.0f / (1024.0f * g_colsum[k]) : 1.0f;
    __syncthreads();

    const float4* c4 = (const float4*)c_s;
    float4 acc[8];
#pragma unroll
    for (int t = 0; t < 8; t++) acc[t] = make_float4(0.f, 0.f, 0.f, 0.f);

#pragma unroll
    for (int i = 0; i < 8; i++) {        // 8 rows per warp
        int n = r0 + w * 8 + i;
        const float4* a4 = (const float4*)(g_A + (size_t)n * KCB);
        float4 a[8];
        float s = 0.0f;
#pragma unroll
        for (int t = 0; t < 8; t++) {
            a[t] = a4[lane + t * 32];
            float4 c = c4[lane + t * 32];
            s += a[t].x * c.x + a[t].y * c.y + a[t].z * c.z + a[t].w * c.w;
        }
        for (int o = 16; o > 0; o >>= 1) s += __shfl_down_sync(0xffffffffu, s, o);
        s = __shfl_sync(0xffffffffu, s, 0);
        float r = 1.0f / (32768.0f * s);
#pragma unroll
        for (int t = 0; t < 8; t++) {
            acc[t].x += a[t].x * r; acc[t].y += a[t].y * r;
            acc[t].z += a[t].z * r; acc[t].w += a[t].w * r;
        }
    }
    float4* wa4 = (float4*)wacc[w];
#pragma unroll
    for (int t = 0; t < 8; t++) wa4[lane + t * 32] = acc[t];
    __syncthreads();

    for (int k = tid; k < KCB; k += 256) {
        float sum = 0.0f;
#pragma unroll
        for (int ww = 0; ww < 8; ww++) sum += wacc[ww][k];
        g_colpart[(size_t)blockIdx.x * KCB + k] = sum;
    }
}

// deterministic fixed-order reduction of column partials
__global__ void reduce_colsum() {
    int k = blockIdx.x;
    int t = threadIdx.x; // 128
    float s = 0.0f;
    for (int b = t; b < NBLK; b += 128)
        s += g_colpart[(size_t)b * KCB + k];
    __shared__ float sh[128];
    sh[t] = s;
    __syncthreads();
    for (int o = 64; o > 0; o >>= 1) {
        if (t < o) sh[t] += sh[t + o];
        __syncthreads();
    }
    if (t == 0) g_colsum[k] = sh[0];
}

// ---------------------------------------------------------------------------
// Final pass: argmax_k A[n,k]*c3_k (first-index tie-break), gather codeword.
//   last == 0: resid -= E[idx]; write next level's bf16 3-plane split.
//   last == 1: out = x - (resid - E[idx]); no resid/split writes (dead).
__global__ __launch_bounds__(256) void argmax_gather(const float* __restrict__ E,
                                                     const float* __restrict__ x,
                                                     float* __restrict__ out,
                                                     int last) {
    __shared__ __align__(16) float c_s[KCB];
    const int tid = threadIdx.x;
    const int r0  = blockIdx.x * ROWS;

    for (int k = tid; k < KCB; k += 256)
        c_s[k] = 1.0f / (1024.0f * g_colsum[k]);
    __syncthreads();

    const int w = tid >> 5, lane = tid & 31;
#pragma unroll
    for (int i = 0; i < ROWS / 8; i++) {
        int n = r0 + w * 8 + i;
        const float* a = g_A + (size_t)n * KCB;
        float best = -1e30f;
        int   bi   = 0;
#pragma unroll
        for (int t = 0; t < 8; t++) {
            int kbase = (lane + t * 32) * 4;
            float4 av = *(const float4*)(a + kbase);
            float4 cv = *(const float4*)(c_s + kbase);
            float v;
            v = av.x * cv.x; if (v > best) { best = v; bi = kbase + 0; }
            v = av.y * cv.y; if (v > best) { best = v; bi = kbase + 1; }
            v = av.z * cv.z; if (v > best) { best = v; bi = kbase + 2; }
            v = av.w * cv.w; if (v > best) { best = v; bi = kbase + 3; }
        }
        for (int o = 16; o > 0; o >>= 1) {
            float ov = __shfl_down_sync(0xffffffffu, best, o);
            int   oi = __shfl_down_sync(0xffffffffu, bi, o);
            if (ov > best || (ov == best && oi < bi)) { best = ov; bi = oi; }
        }
        bi = __shfl_sync(0xffffffffu, bi, 0);

        // each lane owns 16 contiguous dims -> coalesced fp32 & bf16 traffic
        const int d0 = lane * 16;
        const float4* e4  = (const float4*)(E + (size_t)bi * DDIM + d0);
        float4* rp4 = (float4*)(g_resid + (size_t)n * DDIM + d0);

        if (last) {
            const float4* x4 = (const float4*)(x + (size_t)n * DDIM + d0);
            float4* o4 = (float4*)(out + (size_t)n * DDIM + d0);
#pragma unroll
            for (int j = 0; j < 4; j++) {
                float4 ev = e4[j];
                float4 rv = rp4[j];
                float4 xv = x4[j];
                float4 ov;
                ov.x = xv.x - (rv.x - ev.x);
                ov.y = xv.y - (rv.y - ev.y);
                ov.z = xv.z - (rv.z - ev.z);
                ov.w = xv.w - (rv.w - ev.w);
                o4[j] = ov;
            }
        } else {
            uint32_t hw[8], mw[8], lw[8];
#pragma unroll
            for (int j = 0; j < 4; j++) {
                float4 ev = e4[j];
                float4 rv = rp4[j];
                rv.x -= ev.x; rv.y -= ev.y; rv.z -= ev.z; rv.w -= ev.w;
                rp4[j] = rv;
                __nv_bfloat16 h0, m0, l0, h1, m1, l1, h2, m2, l2, h3, m3, l3;
                split3(rv.x, h0, m0, l0); split3(rv.y, h1, m1, l1);
                split3(rv.z, h2, m2, l2); split3(rv.w, h3, m3, l3);
                __nv_bfloat162 hp0 = __halves2bfloat162(h0, h1), hp1 = __halves2bfloat162(h2, h3);
                __nv_bfloat162 mp0 = __halves2bfloat162(m0, m1), mp1 = __halves2bfloat162(m2, m3);
                __nv_bfloat162 lp0 = __halves2bfloat162(l0, l1), lp1 = __halves2bfloat162(l2, l3);
                hw[j * 2 + 0] = *(uint32_t*)&hp0; hw[j * 2 + 1] = *(uint32_t*)&hp1;
                mw[j * 2 + 0] = *(uint32_t*)&mp0; mw[j * 2 + 1] = *(uint32_t*)&mp1;
                lw[j * 2 + 0] = *(uint32_t*)&lp0; lw[j * 2 + 1] = *(uint32_t*)&lp1;
            }
            uint4* hdst = (uint4*)(g_Rs[0] + (size_t)n * DDIM + d0);
            uint4* mdst = (uint4*)(g_Rs[1] + (size_t)n * DDIM + d0);
            uint4* ldst = (uint4*)(g_Rs[2] + (size_t)n * DDIM + d0);
            hdst[0] = make_uint4(hw[0], hw[1], hw[2], hw[3]);
            hdst[1] = make_uint4(hw[4], hw[5], hw[6], hw[7]);
            mdst[0] = make_uint4(mw[0], mw[1], mw[2], mw[3]);
            mdst[1] = make_uint4(mw[4], mw[5], mw[6], mw[7]);
            ldst[0] = make_uint4(lw[0], lw[1], lw[2], lw[3]);
            ldst[1] = make_uint4(lw[4], lw[5], lw[6], lw[7]);
        }
    }
}

// ---------------------------------------------------------------------------
extern "C" void kernel_launch(void* const* d_in, const int* in_sizes, int n_in,
                              void* d_out, int out_size) {
    const float* x         = (const float*)d_in[0];
    const float* codebooks = (const float*)d_in[1];
    // d_in[2] = sigma: dead in forward (straight-through cancels y_soft exactly)
    float* out = (float*)d_out;

    static int smem_set = 0;
    if (!smem_set) {
        cudaFuncSetAttribute(gemm_hmma,
                             cudaFuncAttributeMaxDynamicSharedMemorySize,
                             SMEM_GEMM);
        smem_set = 1;
    }

    init_kernel<<<(NTOK * DDIM + 255) / 256, 256>>>(x);
    split_E_kernel<<<(NQ * KCB * DDIM + 255) / 256, 256>>>(codebooks);
    enorm_kernel<<<NQ * KCB, 128>>>(codebooks);

    for (int lvl = 0; lvl < NQ; lvl++) {
        const float* E = codebooks + (size_t)lvl * KCB * DDIM;

        gemm_hmma<<<dim3(KCB / 128, NTOK / 128), 256, SMEM_GEMM>>>(lvl);

        rowcol_pass<<<NBLK, 256>>>(0);
        reduce_colsum<<<KCB, 128>>>();
        rowcol_pass<<<NBLK, 256>>>(1);
        reduce_colsum<<<KCB, 128>>>();
        rowcol_pass<<<NBLK, 256>>>(1);
        reduce_colsum<<<KCB, 128>>>();

        argmax_gather<<<NBLK, 256>>>(E, x, out, lvl == NQ - 1 ? 1 : 0);
    }
}

// round 17
// speedup vs baseline: 1.9848x; 1.0312x over previous
#include <cuda_runtime.h>
#include <cuda_bf16.h>
#include <math.h>
#include <stdint.h>

// Problem constants (fixed by the dataset)
#define NTOK 32768
#define DDIM 512
#define KCB  1024
#define NQ   4

#define ROWS 64                  // rows per sinkhorn slice
#define NSLICE (NTOK / ROWS)     // 512 slices
#define GBLOCKS 256              // persistent blocks (2 slices each), 2/SM resident

// -------- scratch (static __device__ globals; no allocation allowed) --------
__device__ float g_A[(size_t)NTOK * KCB];      // exp(2G - ||E||^2), 134 MB
__device__ float g_resid[(size_t)NTOK * DDIM]; // running residual, 64 MB
__device__ float g_Enorm[NQ * KCB];
__device__ float g_colsum[KCB];
__device__ float g_colpart[(size_t)NSLICE * KCB];
__device__ unsigned g_bar;                     // monotonic grid barrier counter
// bf16 3-way splits (hi/mid/lo, all normal-range) for 6-product fp32 emulation
__device__ __align__(256) __nv_bfloat16 g_Rs[3][(size_t)NTOK * DDIM];
__device__ __align__(256) __nv_bfloat16 g_Es[3][(size_t)NQ * KCB * DDIM];

// ---------------------------------------------------------------------------
__device__ __forceinline__ uint32_t smem_u32(const void* p) {
    uint32_t a;
    asm("{ .reg .u64 t; cvta.to.shared.u64 t, %1; cvt.u32.u64 %0, t; }"
        : "=r"(a) : "l"(p));
    return a;
}
__device__ __forceinline__ void cp16(uint32_t dst, const void* src) {
    asm volatile("cp.async.cg.shared.global [%0], [%1], 16;"
                 :: "r"(dst), "l"(src));
}
#define CP_COMMIT() asm volatile("cp.async.commit_group;")
#define CP_WAIT(n)  asm volatile("cp.async.wait_group %0;" :: "n"(n))

__device__ __forceinline__ void ldmx4(uint32_t* r, uint32_t addr) {
    asm volatile("ldmatrix.sync.aligned.m8n8.x4.shared.b16 {%0,%1,%2,%3}, [%4];"
                 : "=r"(r[0]), "=r"(r[1]), "=r"(r[2]), "=r"(r[3]) : "r"(addr));
}
__device__ __forceinline__ void mma16816bf(float* c, const uint32_t* a,
                                           const uint32_t* b) {
    asm volatile(
        "mma.sync.aligned.m16n8k16.row.col.f32.bf16.bf16.f32 "
        "{%0,%1,%2,%3}, {%4,%5,%6,%7}, {%8,%9}, {%0,%1,%2,%3};"
        : "+f"(c[0]), "+f"(c[1]), "+f"(c[2]), "+f"(c[3])
        : "r"(a[0]), "r"(a[1]), "r"(a[2]), "r"(a[3]), "r"(b[0]), "r"(b[1]));
}

// 3-way bf16 split (remainders exact in fp32; bf16 range = fp32, no subnormals)
__device__ __forceinline__ void split3(float a, __nv_bfloat16& h,
                                       __nv_bfloat16& m, __nv_bfloat16& l) {
    h = __float2bfloat16(a);
    float r1 = a - __bfloat162float(h);
    m = __float2bfloat16(r1);
    float r2 = r1 - __bfloat162float(m);
    l = __float2bfloat16(r2);
}

// Replay-safe monotonic grid barrier: target = next multiple of GBLOCKS above
// this block's ticket. Release via __threadfence before arrival; consumers
// read cross-block data with __ldcg (L2 is the coherence point).
__device__ __forceinline__ void gridbar() {
    __threadfence();
    __syncthreads();
    if (threadIdx.x == 0) {
        unsigned old = atomicAdd(&g_bar, 1u);
        unsigned target = old + (GBLOCKS - old % GBLOCKS);
        while (atomicAdd(&g_bar, 0u) < target) __nanosleep(128);
    }
    __syncthreads();
}

// ---------------------------------------------------------------------------
// init: residual = x, level-0 split of x (fused). out untouched: the final
// sinkhorn_argmax writes every element of out directly (out = x - resid_final).
__global__ void init_kernel(const float* __restrict__ x) {
    int i = blockIdx.x * blockDim.x + threadIdx.x;
    if (i < NTOK * DDIM) {
        float a = x[i];
        g_resid[i] = a;
        __nv_bfloat16 h, m, l;
        split3(a, h, m, l);
        g_Rs[0][i] = h;
        g_Rs[1][i] = m;
        g_Rs[2][i] = l;
    }
}

// split all codebooks once per launch
__global__ void split_E_kernel(const float* __restrict__ codebooks) {
    int i = blockIdx.x * blockDim.x + threadIdx.x;
    if (i < NQ * KCB * DDIM) {
        __nv_bfloat16 h, m, l;
        split3(codebooks[i], h, m, l);
        g_Es[0][i] = h;
        g_Es[1][i] = m;
        g_Es[2][i] = l;
    }
}

// ---------------------------------------------------------------------------
// ||E_k||^2 for ALL levels in one launch (fp32, deterministic order)
__global__ void enorm_kernel(const float* __restrict__ codebooks) {
    int k = blockIdx.x;                  // 0 .. NQ*KCB-1
    int t = threadIdx.x;                 // 128
    float s = 0.0f;
    const float* row = codebooks + (size_t)k * DDIM;
    for (int d = t; d < DDIM; d += 128) { float v = row[d]; s += v * v; }
    __shared__ float sh[128];
    sh[t] = s;
    __syncthreads();
    for (int o = 64; o > 0; o >>= 1) {
        if (t < o) sh[t] += sh[t + o];
        __syncthreads();
    }
    if (t == 0) g_Enorm[k] = sh[0];
}

// ---------------------------------------------------------------------------
// HMMA GEMM: G = sum of 6 bf16 plane-products (hh,hm,mh,mm,hl,lh).
// Stage = one physical k32 slice holding ALL 6 planes as 3 pair-tiles
// (128 rows x 128 B, SW swizzle): T0=(Rh|Rm) T1=(Rl|Eh) T2=(Em|El).
// 16 stages, 2-stage cp.async ring, ONE __syncthreads per stage.
// Epilogue fused: g_A = exp(2G - ||E||^2).
#define TILE_B  16384                   // 128 rows * 128 B
#define BUF_B   (3 * TILE_B)            // 48 KB per stage
#define NSTAGE  2
#define NHC     16                      // 512 / 32 half-chunks
#define SMEM_GEMM (NSTAGE * BUF_B)      // 96 KB

__global__ __launch_bounds__(256, 2) void gemm_hmma(int lvl) {
    extern __shared__ char sm[];
    const uint32_t sbase = smem_u32(sm);
    const int tid  = threadIdx.x;
    const int wid  = tid >> 5;
    const int lane = tid & 31;
    const int row0 = blockIdx.y * 128;  // token tile
    const int col0 = blockIdx.x * 128;  // codebook tile
    const size_t eoff = (size_t)lvl * KCB * DDIM;

    const int wm0 = (wid & 1) * 64;
    const int wn0 = (wid >> 1) * 32;

    float acc[4][4][4];
#pragma unroll
    for (int mt = 0; mt < 4; mt++)
#pragma unroll
        for (int nt = 0; nt < 4; nt++)
#pragma unroll
            for (int e = 0; e < 4; e++) acc[mt][nt][e] = 0.0f;

    // plane table: 0..2 = Rh,Rm,Rl (token rows); 3..5 = Eh,Em,El (codebook rows)
    const __nv_bfloat16* plane[6] = {
        g_Rs[0], g_Rs[1], g_Rs[2],
        g_Es[0] + eoff, g_Es[1] + eoff, g_Es[2] + eoff
    };

    // stage hc: pair-tile t holds planes (2t | 2t+1); left half = 4x16B units
    auto issue_load = [&](int hc, int slot) {
        const int koff = hc * 32;
        const uint32_t dbase = sbase + slot * BUF_B;
#pragma unroll
        for (int i = 0; i < 12; i++) {
            int v   = tid + i * 256;
            int t   = v >> 10;           // tile 0..2
            int rr  = (v >> 3) & 127;    // row
            int c16 = v & 7;             // 16B unit
            int p   = t * 2 + (c16 >> 2);
            int rb  = (p >= 3) ? col0 : row0;
            const __nv_bfloat16* src =
                plane[p] + (size_t)(rb + rr) * DDIM + koff + (c16 & 3) * 8;
            uint32_t dst = dbase + t * TILE_B + rr * 128 + ((c16 ^ (rr & 7)) << 4);
            cp16(dst, src);
        }
        CP_COMMIT();
    };

    auto compute = [&](int slot) {
        const uint32_t t0 = sbase + slot * BUF_B;
        const uint32_t t1 = t0 + TILE_B;
        const uint32_t t2 = t1 + TILE_B;
#pragma unroll
        for (int ks = 0; ks < 2; ks++) {
            const int au = ks * 2 + (lane >> 4);        // A unit within half
            const int bu = ks * 2 + ((lane >> 3) & 1);  // B unit within half

            uint32_t aF[4][4], bH[4][2], bM[4][2], bL[4][2];

            // B fragment loader: tile + half (0 = units 0..3, 1 = units 4..7)
            auto loadB = [&](uint32_t (*dst)[2], uint32_t tile, int half) {
#pragma unroll
                for (int bt = 0; bt < 2; bt++) {
                    int nrow = wn0 + bt * 16 + (lane & 7) + ((lane >> 4) << 3);
                    int u = half * 4 + bu;
                    uint32_t r[4];
                    ldmx4(r, tile + nrow * 128 + ((u ^ (nrow & 7)) << 4));
                    dst[bt * 2 + 0][0] = r[0]; dst[bt * 2 + 0][1] = r[1];
                    dst[bt * 2 + 1][0] = r[2]; dst[bt * 2 + 1][1] = r[3];
                }
            };
            auto loadA = [&](uint32_t tile, int half) {
#pragma unroll
                for (int mt = 0; mt < 4; mt++) {
                    int row = wm0 + mt * 16 + (lane & 15);
                    int u = half * 4 + au;
                    ldmx4(aF[mt], tile + row * 128 + ((u ^ (row & 7)) << 4));
                }
            };
            auto mmaAll = [&](uint32_t (*bF)[2]) {
#pragma unroll
                for (int mt = 0; mt < 4; mt++)
#pragma unroll
                    for (int nt = 0; nt < 4; nt++)
                        mma16816bf(acc[mt][nt], aF[mt], bF[nt]);
            };

            loadB(bH, t1, 1);    // Eh
            loadB(bM, t2, 0);    // Em
            loadA(t0, 0);        // Rh
            mmaAll(bH);          // hh
            mmaAll(bM);          // hm
            loadB(bL, t2, 1);    // El
            mmaAll(bL);          // hl
            loadA(t0, 1);        // Rm
            mmaAll(bH);          // mh
            mmaAll(bM);          // mm
            loadA(t1, 0);        // Rl
            mmaAll(bH);          // lh
        }
    };

    issue_load(0, 0);
    for (int hc = 0; hc < NHC; hc++) {
        CP_WAIT(0);             // only group hc is outstanding -> it landed
        __syncthreads();        // data visible to all; compute(hc-1) done
        if (hc + 1 < NHC) issue_load(hc + 1, (hc + 1) & 1);
        compute(hc & 1);
    }

    // epilogue: exp(2G - ||E||^2) -> g_A
    const float* en = g_Enorm + lvl * KCB;
#pragma unroll
    for (int nt = 0; nt < 4; nt++) {
        int col = col0 + wn0 + nt * 8 + (lane & 3) * 2;
        float en0 = __ldg(&en[col]);
        float en1 = __ldg(&en[col + 1]);
#pragma unroll
        for (int mt = 0; mt < 4; mt++) {
            int r0 = row0 + wm0 + mt * 16 + (lane >> 2);
            float2 v0, v1;
            v0.x = expf(2.0f * acc[mt][nt][0] - en0);
            v0.y = expf(2.0f * acc[mt][nt][1] - en1);
            v1.x = expf(2.0f * acc[mt][nt][2] - en0);
            v1.y = expf(2.0f * acc[mt][nt][3] - en1);
            *(float2*)(g_A + (size_t)r0 * KCB + col)       = v0;
            *(float2*)(g_A + (size_t)(r0 + 8) * KCB + col) = v1;
        }
    }
}

// ---------------------------------------------------------------------------
// Fused per-level sinkhorn (3 iterations) + argmax/gather, ONE persistent
// kernel with grid barriers. Block b owns slices {2b, 2b+1} for all phases
// (L2 locality: its 512 KB A-slice is re-scanned 4x). Reduce phase: block b
// owns k in [4b, 4b+4), fixed-order 64-thread tree (deterministic).
__global__ __launch_bounds__(256, 2) void sinkhorn_argmax(
        const float* __restrict__ E, const float* __restrict__ x,
        float* __restrict__ out, int last) {
    __shared__ __align__(16) float c_s[KCB];
    __shared__ float wacc[8][KCB];
    __shared__ float red[4][64];
    const int tid = threadIdx.x, w = tid >> 5, lane = tid & 31;

    for (int it = 0; it < 3; it++) {
        // c for this iteration (it==0: all ones)
        if (it == 0) {
            for (int k = tid; k < KCB; k += 256) c_s[k] = 1.0f;
        } else {
            for (int k = tid; k < KCB; k += 256)
                c_s[k] = 1.0f / (1024.0f * __ldcg(&g_colsum[k]));
        }
        __syncthreads();

        for (int sl = 0; sl < 2; sl++) {
            const int slice = blockIdx.x * 2 + sl;
            const int r0 = slice * ROWS;
            const float4* c4 = (const float4*)c_s;
            float4 acc[8];
#pragma unroll
            for (int t = 0; t < 8; t++) acc[t] = make_float4(0.f, 0.f, 0.f, 0.f);

#pragma unroll
            for (int i = 0; i < 8; i++) {        // 8 rows per warp
                int n = r0 + w * 8 + i;
                const float4* a4 = (const float4*)(g_A + (size_t)n * KCB);
                float4 a[8];
                float s = 0.0f;
#pragma unroll
                for (int t = 0; t < 8; t++) {
                    a[t] = a4[lane + t * 32];
                    float4 c = c4[lane + t * 32];
                    s += a[t].x * c.x + a[t].y * c.y + a[t].z * c.z + a[t].w * c.w;
                }
                for (int o = 16; o > 0; o >>= 1)
                    s += __shfl_down_sync(0xffffffffu, s, o);
                s = __shfl_sync(0xffffffffu, s, 0);
                float r = 1.0f / (32768.0f * s);
#pragma unroll
                for (int t = 0; t < 8; t++) {
                    acc[t].x += a[t].x * r; acc[t].y += a[t].y * r;
                    acc[t].z += a[t].z * r; acc[t].w += a[t].w * r;
                }
            }
            __syncthreads();     // previous slice's wacc readers are done
            float4* wa4 = (float4*)wacc[w];
#pragma unroll
            for (int t = 0; t < 8; t++) wa4[lane + t * 32] = acc[t];
            __syncthreads();

            for (int k = tid; k < KCB; k += 256) {
                float sum = 0.0f;
#pragma unroll
                for (int ww = 0; ww < 8; ww++) sum += wacc[ww][k];
                g_colpart[(size_t)slice * KCB + k] = sum;
            }
        }
        gridbar();

        // colsum reduce: this block owns k in [4b, 4b+4)
        {
            const int kk = blockIdx.x * 4 + (tid >> 6);
            const int tt = tid & 63;
            float s = 0.0f;
            for (int b = tt; b < NSLICE; b += 64)
                s += __ldcg(&g_colpart[(size_t)b * KCB + kk]);
            red[tid >> 6][tt] = s;
            __syncthreads();
            for (int o = 32; o > 0; o >>= 1) {
                if (tt < o) red[tid >> 6][tt] += red[tid >> 6][tt + o];
                __syncthreads();
            }
            if (tt == 0) g_colsum[kk] = red[tid >> 6][0];
        }
        gridbar();
    }

    // final: argmax with c3, gather codeword, update resid/splits (or out)
    for (int k = tid; k < KCB; k += 256)
        c_s[k] = 1.0f / (1024.0f * __ldcg(&g_colsum[k]));
    __syncthreads();

    for (int sl = 0; sl < 2; sl++) {
        const int slice = blockIdx.x * 2 + sl;
        const int r0 = slice * ROWS;
#pragma unroll
        for (int i = 0; i < ROWS / 8; i++) {
            int n = r0 + w * 8 + i;
            const float* a = g_A + (size_t)n * KCB;
            float best = -1e30f;
            int   bi   = 0;
#pragma unroll
            for (int t = 0; t < 8; t++) {
                int kbase = (lane + t * 32) * 4;
                float4 av = *(const float4*)(a + kbase);
                float4 cv = *(const float4*)(c_s + kbase);
                float v;
                v = av.x * cv.x; if (v > best) { best = v; bi = kbase + 0; }
                v = av.y * cv.y; if (v > best) { best = v; bi = kbase + 1; }
                v = av.z * cv.z; if (v > best) { best = v; bi = kbase + 2; }
                v = av.w * cv.w; if (v > best) { best = v; bi = kbase + 3; }
            }
            for (int o = 16; o > 0; o >>= 1) {
                float ov = __shfl_down_sync(0xffffffffu, best, o);
                int   oi = __shfl_down_sync(0xffffffffu, bi, o);
                if (ov > best || (ov == best && oi < bi)) { best = ov; bi = oi; }
            }
            bi = __shfl_sync(0xffffffffu, bi, 0);

            // each lane owns 16 contiguous dims -> coalesced traffic
            const int d0 = lane * 16;
            const float4* e4  = (const float4*)(E + (size_t)bi * DDIM + d0);
            float4* rp4 = (float4*)(g_resid + (size_t)n * DDIM + d0);

            if (last) {
                const float4* x4 = (const float4*)(x + (size_t)n * DDIM + d0);
                float4* o4 = (float4*)(out + (size_t)n * DDIM + d0);
#pragma unroll
                for (int j = 0; j < 4; j++) {
                    float4 ev = e4[j];
                    float4 rv = rp4[j];
                    float4 xv = x4[j];
                    float4 ov;
                    ov.x = xv.x - (rv.x - ev.x);
                    ov.y = xv.y - (rv.y - ev.y);
                    ov.z = xv.z - (rv.z - ev.z);
                    ov.w = xv.w - (rv.w - ev.w);
                    o4[j] = ov;
                }
            } else {
                uint32_t hw[8], mw[8], lw[8];
#pragma unroll
                for (int j = 0; j < 4; j++) {
                    float4 ev = e4[j];
                    float4 rv = rp4[j];
                    rv.x -= ev.x; rv.y -= ev.y; rv.z -= ev.z; rv.w -= ev.w;
                    rp4[j] = rv;
                    __nv_bfloat16 h0, m0, l0, h1, m1, l1, h2, m2, l2, h3, m3, l3;
                    split3(rv.x, h0, m0, l0); split3(rv.y, h1, m1, l1);
                    split3(rv.z, h2, m2, l2); split3(rv.w, h3, m3, l3);
                    __nv_bfloat162 hp0 = __halves2bfloat162(h0, h1), hp1 = __halves2bfloat162(h2, h3);
                    __nv_bfloat162 mp0 = __halves2bfloat162(m0, m1), mp1 = __halves2bfloat162(m2, m3);
                    __nv_bfloat162 lp0 = __halves2bfloat162(l0, l1), lp1 = __halves2bfloat162(l2, l3);
                    hw[j * 2 + 0] = *(uint32_t*)&hp0; hw[j * 2 + 1] = *(uint32_t*)&hp1;
                    mw[j * 2 + 0] = *(uint32_t*)&mp0; mw[j * 2 + 1] = *(uint32_t*)&mp1;
                    lw[j * 2 + 0] = *(uint32_t*)&lp0; lw[j * 2 + 1] = *(uint32_t*)&lp1;
                }
                uint4* hdst = (uint4*)(g_Rs[0] + (size_t)n * DDIM + d0);
                uint4* mdst = (uint4*)(g_Rs[1] + (size_t)n * DDIM + d0);
                uint4* ldst = (uint4*)(g_Rs[2] + (size_t)n * DDIM + d0);
                hdst[0] = make_uint4(hw[0], hw[1], hw[2], hw[3]);
                hdst[1] = make_uint4(hw[4], hw[5], hw[6], hw[7]);
                mdst[0] = make_uint4(mw[0], mw[1], mw[2], mw[3]);
                mdst[1] = make_uint4(mw[4], mw[5], mw[6], mw[7]);
                ldst[0] = make_uint4(lw[0], lw[1], lw[2], lw[3]);
                ldst[1] = make_uint4(lw[4], lw[5], lw[6], lw[7]);
            }
        }
    }
}

// ---------------------------------------------------------------------------
extern "C" void kernel_launch(void* const* d_in, const int* in_sizes, int n_in,
                              void* d_out, int out_size) {
    const float* x         = (const float*)d_in[0];
    const float* codebooks = (const float*)d_in[1];
    // d_in[2] = sigma: dead in forward (straight-through cancels y_soft exactly)
    float* out = (float*)d_out;

    static int smem_set = 0;
    if (!smem_set) {
        cudaFuncSetAttribute(gemm_hmma,
                             cudaFuncAttributeMaxDynamicSharedMemorySize,
                             SMEM_GEMM);
        smem_set = 1;
    }

    init_kernel<<<(NTOK * DDIM + 255) / 256, 256>>>(x);
    split_E_kernel<<<(NQ * KCB * DDIM + 255) / 256, 256>>>(codebooks);
    enorm_kernel<<<NQ * KCB, 128>>>(codebooks);

    for (int lvl = 0; lvl < NQ; lvl++) {
        const float* E = codebooks + (size_t)lvl * KCB * DDIM;

        gemm_hmma<<<dim3(KCB / 128, NTOK / 128), 256, SMEM_GEMM>>>(lvl);

        sinkhorn_argmax<<<GBLOCKS, 256>>>(E, x, out, lvl == NQ - 1 ? 1 : 0);
    }
}